// round 9
// baseline (speedup 1.0000x reference)
#include <cuda_runtime.h>
#include <math.h>
#include <float.h>

#define EDIM   1024
#define HEADS  16
#define DH     64
#define BB     2
#define SS     2048
#define MTOT   (BB * SS)      // 4096
#define PAD    65             // smem row pad (words) -> conflict-free column reads

// Scratch (allocation-free rule: __device__ globals)
__device__ float g_Q[MTOT * EDIM];
__device__ float g_K[MTOT * EDIM];
__device__ float g_V[MTOT * EDIM];
__device__ float g_C[MTOT * EDIM];

// ---------------------------------------------------------------------------
// SGEMM + bias: C[M,N] = A[M,K] @ B[K,N] + bias[N]
// Fixed K = N = 1024, M = 4096. 128x128x8 tile, 256 threads, 8x8 microtile.
// ---------------------------------------------------------------------------
__global__ __launch_bounds__(256) void sgemm_bias(
    const float* __restrict__ A, const float* __restrict__ B,
    const float* __restrict__ bias, float* __restrict__ C)
{
    const int K = EDIM, N = EDIM;
    __shared__ float As[8][128];   // transposed A tile: As[k][m]
    __shared__ float Bs[8][128];   // Bs[k][n]

    const int tid = threadIdx.x;
    const int bm  = blockIdx.y * 128;
    const int bn  = blockIdx.x * 128;
    const int tx  = tid & 15;      // 0..15  -> n microtile
    const int ty  = tid >> 4;      // 0..15  -> m microtile

    const int a_row = tid >> 1;          // 0..127
    const int a_col = (tid & 1) * 4;     // 0 or 4
    const int b_row = tid >> 5;          // 0..7
    const int b_col = (tid & 31) * 4;    // 0..124

    const float* Aptr = A + (size_t)(bm + a_row) * K + a_col;
    const float* Bptr = B + (size_t)b_row * N + bn + b_col;

    float acc[8][8];
#pragma unroll
    for (int i = 0; i < 8; i++)
#pragma unroll
        for (int j = 0; j < 8; j++) acc[i][j] = 0.f;

    for (int k0 = 0; k0 < K; k0 += 8) {
        float4 av = *(const float4*)(Aptr + k0);
        float4 bv = *(const float4*)(Bptr + (size_t)k0 * N);
        __syncthreads();
        As[a_col + 0][a_row] = av.x;
        As[a_col + 1][a_row] = av.y;
        As[a_col + 2][a_row] = av.z;
        As[a_col + 3][a_row] = av.w;
        *(float4*)&Bs[b_row][b_col] = bv;
        __syncthreads();

#pragma unroll
        for (int k = 0; k < 8; k++) {
            float ar[8], br[8];
#pragma unroll
            for (int i = 0; i < 8; i++) ar[i] = As[k][ty * 8 + i];
#pragma unroll
            for (int j = 0; j < 8; j++) br[j] = Bs[k][tx * 8 + j];
#pragma unroll
            for (int i = 0; i < 8; i++)
#pragma unroll
                for (int j = 0; j < 8; j++) acc[i][j] += ar[i] * br[j];
        }
    }

    // Epilogue: + bias, vectorized stores
    const int cn = bn + tx * 8;
    float4 bias0 = *(const float4*)&bias[cn];
    float4 bias1 = *(const float4*)&bias[cn + 4];
#pragma unroll
    for (int i = 0; i < 8; i++) {
        float* crow = C + (size_t)(bm + ty * 8 + i) * N + cn;
        float4 v0 = make_float4(acc[i][0] + bias0.x, acc[i][1] + bias0.y,
                                acc[i][2] + bias0.z, acc[i][3] + bias0.w);
        float4 v1 = make_float4(acc[i][4] + bias1.x, acc[i][5] + bias1.y,
                                acc[i][6] + bias1.z, acc[i][7] + bias1.w);
        *(float4*)crow       = v0;
        *(float4*)(crow + 4) = v1;
    }
}

// ---------------------------------------------------------------------------
// Flash attention (fp32, online softmax).
// Grid: (S/64, B*H), 256 threads (8 warps). Warp w owns query rows [8w, 8w+8);
// lane owns head-dim / key columns {lane, lane+32}.
// ---------------------------------------------------------------------------
__global__ __launch_bounds__(256) void attn_kernel(
    const float* __restrict__ Q, const float* __restrict__ Kg,
    const float* __restrict__ Vg, float* __restrict__ O)
{
    extern __shared__ float sm[];
    float* Qs = sm;                 // 64 x PAD
    float* Ks = sm + 64 * PAD;      // 64 x PAD  (rows = key idx, cols = dh)
    float* Vs = sm + 2 * 64 * PAD;  // 64 x PAD  (rows = key idx, cols = dh)
    float* Ps = sm + 3 * 64 * PAD;  // 64 x PAD  (rows = query,  cols = key)

    const int tid  = threadIdx.x;
    const int lane = tid & 31;
    const int warp = tid >> 5;
    const int qt   = blockIdx.x;          // query tile 0..31
    const int bh   = blockIdx.y;          // 0..31
    const int b    = bh >> 4;
    const int h    = bh & 15;
    const int q0   = qt * 64;
    const size_t base = (size_t)b * SS * EDIM + (size_t)h * DH;

    // Load Q tile (64 x 64)
    for (int i = tid; i < 64 * 16; i += 256) {       // 1024 float4 slots
        int r = i >> 4;
        int c = (i & 15) * 4;
        float4 v = *(const float4*)&Q[base + (size_t)(q0 + r) * EDIM + c];
        float* p = &Qs[r * PAD + c];
        p[0] = v.x; p[1] = v.y; p[2] = v.z; p[3] = v.w;
    }

    float o0[8], o1[8], mrow[8], lrow[8];
#pragma unroll
    for (int i = 0; i < 8; i++) { o0[i] = 0.f; o1[i] = 0.f; mrow[i] = -FLT_MAX; lrow[i] = 0.f; }
    const int wr = warp * 8;

    for (int kt = 0; kt < SS / 64; kt++) {
        __syncthreads();   // previous iteration's Vs/Ps reads done
        const int k0 = kt * 64;
        for (int i = tid; i < 64 * 16; i += 256) {
            int r = i >> 4;
            int c = (i & 15) * 4;
            size_t g = base + (size_t)(k0 + r) * EDIM + c;
            float4 kv = *(const float4*)&Kg[g];
            float4 vv = *(const float4*)&Vg[g];
            float* pk = &Ks[r * PAD + c];
            float* pv = &Vs[r * PAD + c];
            pk[0] = kv.x; pk[1] = kv.y; pk[2] = kv.z; pk[3] = kv.w;
            pv[0] = vv.x; pv[1] = vv.y; pv[2] = vv.z; pv[3] = vv.w;
        }
        __syncthreads();

        // Scores: s[r][c] = dot(Q[r], K[c]) ; lane cols c0=lane, c1=lane+32
        float s0[8], s1[8];
#pragma unroll
        for (int i = 0; i < 8; i++) { s0[i] = 0.f; s1[i] = 0.f; }
#pragma unroll 2
        for (int kk = 0; kk < 64; kk++) {
            float k0v = Ks[lane * PAD + kk];
            float k1v = Ks[(lane + 32) * PAD + kk];
#pragma unroll
            for (int i = 0; i < 8; i++) {
                float qv = Qs[(wr + i) * PAD + kk];
                s0[i] += qv * k0v;
                s1[i] += qv * k1v;
            }
        }

        // Online softmax (per row, warp-wide)
        const float sc = 0.125f;   // 1/sqrt(64)
#pragma unroll
        for (int i = 0; i < 8; i++) {
            s0[i] *= sc; s1[i] *= sc;
            float v = fmaxf(s0[i], s1[i]);
#pragma unroll
            for (int off = 16; off > 0; off >>= 1)
                v = fmaxf(v, __shfl_xor_sync(0xffffffffu, v, off));
            float mn = fmaxf(mrow[i], v);
            float f  = __expf(mrow[i] - mn);
            float p0 = __expf(s0[i] - mn);
            float p1 = __expf(s1[i] - mn);
            float rs = p0 + p1;
#pragma unroll
            for (int off = 16; off > 0; off >>= 1)
                rs += __shfl_xor_sync(0xffffffffu, rs, off);
            lrow[i] = lrow[i] * f + rs;
            mrow[i] = mn;
            o0[i] *= f; o1[i] *= f;
            Ps[(wr + i) * PAD + lane]      = p0;
            Ps[(wr + i) * PAD + lane + 32] = p1;
        }
        __syncwarp();

        // O += P @ V
#pragma unroll 2
        for (int kk = 0; kk < 64; kk++) {
            float v0 = Vs[kk * PAD + lane];
            float v1 = Vs[kk * PAD + lane + 32];
#pragma unroll
            for (int i = 0; i < 8; i++) {
                float p = Ps[(wr + i) * PAD + kk];
                o0[i] += p * v0;
                o1[i] += p * v1;
            }
        }
    }

    // Epilogue: normalize, write context
#pragma unroll
    for (int i = 0; i < 8; i++) {
        float inv = 1.0f / lrow[i];
        float* orow = O + base + (size_t)(q0 + wr + i) * EDIM;
        orow[lane]      = o0[i] * inv;
        orow[lane + 32] = o1[i] * inv;
    }
}

// ---------------------------------------------------------------------------
// Launch: 3 QKV GEMMs -> attention -> output GEMM. All graph-capturable.
// ---------------------------------------------------------------------------
extern "C" void kernel_launch(void* const* d_in, const int* in_sizes, int n_in,
                              void* d_out, int out_size)
{
    const float* x  = (const float*)d_in[0];
    const float* Wq = (const float*)d_in[1];
    const float* bq = (const float*)d_in[2];
    const float* Wk = (const float*)d_in[3];
    const float* bk = (const float*)d_in[4];
    const float* Wv = (const float*)d_in[5];
    const float* bv = (const float*)d_in[6];
    const float* Wo = (const float*)d_in[7];
    const float* bo = (const float*)d_in[8];
    float* out = (float*)d_out;

    float *qp, *kp, *vp, *cp;
    cudaGetSymbolAddress((void**)&qp, g_Q);
    cudaGetSymbolAddress((void**)&kp, g_K);
    cudaGetSymbolAddress((void**)&vp, g_V);
    cudaGetSymbolAddress((void**)&cp, g_C);

    dim3 gg(EDIM / 128, MTOT / 128);   // (8, 32)
    sgemm_bias<<<gg, 256>>>(x, Wq, bq, qp);
    sgemm_bias<<<gg, 256>>>(x, Wk, bk, kp);
    sgemm_bias<<<gg, 256>>>(x, Wv, bv, vp);

    size_t smem = (size_t)4 * 64 * PAD * sizeof(float);   // 66560 B
    cudaFuncSetAttribute(attn_kernel, cudaFuncAttributeMaxDynamicSharedMemorySize, (int)smem);
    attn_kernel<<<dim3(SS / 64, BB * HEADS), 256, smem>>>(qp, kp, vp, cp);

    sgemm_bias<<<gg, 256>>>(cp, Wo, bo, out);
}

// round 10
// speedup vs baseline: 1.1110x; 1.1110x over previous
#include <cuda_runtime.h>
#include <math.h>
#include <float.h>

#define EDIM   1024
#define HEADS  16
#define DH     64
#define BB     2
#define SS     2048
#define MTOT   (BB * SS)      // 4096
#define PAD    68             // smem row pad (words): 16B-aligned, 17x16B odd stride -> conflict-free

// Scratch (allocation-free rule: __device__ globals)
__device__ float g_Q[MTOT * EDIM];
__device__ float g_K[MTOT * EDIM];
__device__ float g_V[MTOT * EDIM];
__device__ float g_C[MTOT * EDIM];

// ---------------------------------------------------------------------------
// SGEMM + bias: C[M,N] = A[M,K] @ B[K,N] + bias[N]
// Fixed K = N = 1024, M = 4096. 128x128x8 tile, 256 threads, 8x8 microtile.
// Double-buffered smem (1 sync/iter), float4 fragment reads.
// ---------------------------------------------------------------------------
__global__ __launch_bounds__(256) void sgemm_bias(
    const float* __restrict__ A, const float* __restrict__ B,
    const float* __restrict__ bias, float* __restrict__ C)
{
    const int K = EDIM, N = EDIM;
    __shared__ float As[2][8][128];   // transposed A tile: As[buf][k][m]
    __shared__ float Bs[2][8][128];   // Bs[buf][k][n]

    const int tid = threadIdx.x;
    const int bm  = blockIdx.y * 128;
    const int bn  = blockIdx.x * 128;
    const int tx  = tid & 15;      // 0..15  -> n microtile
    const int ty  = tid >> 4;      // 0..15  -> m microtile

    const int a_row = tid >> 1;          // 0..127
    const int a_col = (tid & 1) * 4;     // 0 or 4
    const int b_row = tid >> 5;          // 0..7
    const int b_col = (tid & 31) * 4;    // 0..124

    const float* Aptr = A + (size_t)(bm + a_row) * K + a_col;
    const float* Bptr = B + (size_t)b_row * N + bn + b_col;

    float acc[8][8];
#pragma unroll
    for (int i = 0; i < 8; i++)
#pragma unroll
        for (int j = 0; j < 8; j++) acc[i][j] = 0.f;

    // Prologue: fill buffer 0
    {
        float4 av = *(const float4*)(Aptr);
        float4 bv = *(const float4*)(Bptr);
        As[0][a_col + 0][a_row] = av.x;
        As[0][a_col + 1][a_row] = av.y;
        As[0][a_col + 2][a_row] = av.z;
        As[0][a_col + 3][a_row] = av.w;
        *(float4*)&Bs[0][b_row][b_col] = bv;
    }
    __syncthreads();

    int cur = 0;
    for (int k0 = 0; k0 < K; k0 += 8) {
        const bool has_next = (k0 + 8) < K;
        float4 av, bv;
        if (has_next) {
            av = *(const float4*)(Aptr + (k0 + 8));
            bv = *(const float4*)(Bptr + (size_t)(k0 + 8) * N);
        }

#pragma unroll
        for (int k = 0; k < 8; k++) {
            float4 a0 = *(const float4*)&As[cur][k][ty * 8];
            float4 a1 = *(const float4*)&As[cur][k][ty * 8 + 4];
            float4 b0 = *(const float4*)&Bs[cur][k][tx * 8];
            float4 b1 = *(const float4*)&Bs[cur][k][tx * 8 + 4];
            float ar[8] = {a0.x, a0.y, a0.z, a0.w, a1.x, a1.y, a1.z, a1.w};
            float br[8] = {b0.x, b0.y, b0.z, b0.w, b1.x, b1.y, b1.z, b1.w};
#pragma unroll
            for (int i = 0; i < 8; i++)
#pragma unroll
                for (int j = 0; j < 8; j++) acc[i][j] += ar[i] * br[j];
        }

        if (has_next) {
            const int nxt = cur ^ 1;
            As[nxt][a_col + 0][a_row] = av.x;
            As[nxt][a_col + 1][a_row] = av.y;
            As[nxt][a_col + 2][a_row] = av.z;
            As[nxt][a_col + 3][a_row] = av.w;
            *(float4*)&Bs[nxt][b_row][b_col] = bv;
            __syncthreads();
            cur = nxt;
        }
    }

    // Epilogue: + bias, vectorized stores
    const int cn = bn + tx * 8;
    float4 bias0 = *(const float4*)&bias[cn];
    float4 bias1 = *(const float4*)&bias[cn + 4];
#pragma unroll
    for (int i = 0; i < 8; i++) {
        float* crow = C + (size_t)(bm + ty * 8 + i) * N + cn;
        float4 v0 = make_float4(acc[i][0] + bias0.x, acc[i][1] + bias0.y,
                                acc[i][2] + bias0.z, acc[i][3] + bias0.w);
        float4 v1 = make_float4(acc[i][4] + bias1.x, acc[i][5] + bias1.y,
                                acc[i][6] + bias1.z, acc[i][7] + bias1.w);
        *(float4*)crow       = v0;
        *(float4*)(crow + 4) = v1;
    }
}

// ---------------------------------------------------------------------------
// Flash attention (fp32, online softmax), float4 smem reads everywhere.
// Grid: (S/64, B*H), 256 threads (8 warps). Warp w owns query rows [8w, 8w+8);
// lane owns head-dim / key columns {lane, lane+32}.
// ---------------------------------------------------------------------------
__global__ __launch_bounds__(256) void attn_kernel(
    const float* __restrict__ Q, const float* __restrict__ Kg,
    const float* __restrict__ Vg, float* __restrict__ O)
{
    extern __shared__ float sm[];
    float* Qs = sm;                 // 64 x PAD  (rows = query,  cols = dh)
    float* Ks = sm + 64 * PAD;      // 64 x PAD  (rows = key,    cols = dh)
    float* Vs = sm + 2 * 64 * PAD;  // 64 x PAD  (rows = key,    cols = dh)
    float* Ps = sm + 3 * 64 * PAD;  // 64 x PAD  (rows = query,  cols = key)

    const int tid  = threadIdx.x;
    const int lane = tid & 31;
    const int warp = tid >> 5;
    const int qt   = blockIdx.x;          // query tile 0..31
    const int bh   = blockIdx.y;          // 0..31
    const int b    = bh >> 4;
    const int h    = bh & 15;
    const int q0   = qt * 64;
    const size_t base = (size_t)b * SS * EDIM + (size_t)h * DH;

    // Load Q tile (64 x 64)
    for (int i = tid; i < 64 * 16; i += 256) {       // 1024 float4 slots
        int r = i >> 4;
        int c = (i & 15) * 4;
        float4 v = *(const float4*)&Q[base + (size_t)(q0 + r) * EDIM + c];
        *(float4*)&Qs[r * PAD + c] = v;
    }

    float o0[8], o1[8], mrow[8], lrow[8];
#pragma unroll
    for (int i = 0; i < 8; i++) { o0[i] = 0.f; o1[i] = 0.f; mrow[i] = -FLT_MAX; lrow[i] = 0.f; }
    const int wr = warp * 8;
    const int r0 = lane;            // this lane's key/dh column 0
    const int r1 = lane + 32;       // this lane's key/dh column 1

    for (int kt = 0; kt < SS / 64; kt++) {
        __syncthreads();   // previous iteration's Ks/Vs/Ps reads done (also covers Qs on kt=0)
        const int k0 = kt * 64;
        for (int i = tid; i < 64 * 16; i += 256) {
            int r = i >> 4;
            int c = (i & 15) * 4;
            size_t g = base + (size_t)(k0 + r) * EDIM + c;
            float4 kv = *(const float4*)&Kg[g];
            float4 vv = *(const float4*)&Vg[g];
            *(float4*)&Ks[r * PAD + c] = kv;
            *(float4*)&Vs[r * PAD + c] = vv;
        }
        __syncthreads();

        // Scores: s[r][c] = dot(Q[r], K[c]) ; lane cols c0=lane, c1=lane+32
        float s0[8], s1[8];
#pragma unroll
        for (int i = 0; i < 8; i++) { s0[i] = 0.f; s1[i] = 0.f; }
#pragma unroll 4
        for (int kk = 0; kk < 64; kk += 4) {
            float4 k0v = *(const float4*)&Ks[r0 * PAD + kk];
            float4 k1v = *(const float4*)&Ks[r1 * PAD + kk];
#pragma unroll
            for (int i = 0; i < 8; i++) {
                float4 qv = *(const float4*)&Qs[(wr + i) * PAD + kk];
                s0[i] += qv.x * k0v.x + qv.y * k0v.y + qv.z * k0v.z + qv.w * k0v.w;
                s1[i] += qv.x * k1v.x + qv.y * k1v.y + qv.z * k1v.z + qv.w * k1v.w;
            }
        }

        // Online softmax (per row, warp-wide)
        const float sc = 0.125f;   // 1/sqrt(64)
#pragma unroll
        for (int i = 0; i < 8; i++) {
            s0[i] *= sc; s1[i] *= sc;
            float v = fmaxf(s0[i], s1[i]);
#pragma unroll
            for (int off = 16; off > 0; off >>= 1)
                v = fmaxf(v, __shfl_xor_sync(0xffffffffu, v, off));
            float mn = fmaxf(mrow[i], v);
            float f  = __expf(mrow[i] - mn);
            float p0 = __expf(s0[i] - mn);
            float p1 = __expf(s1[i] - mn);
            float rs = p0 + p1;
#pragma unroll
            for (int off = 16; off > 0; off >>= 1)
                rs += __shfl_xor_sync(0xffffffffu, rs, off);
            lrow[i] = lrow[i] * f + rs;
            mrow[i] = mn;
            o0[i] *= f; o1[i] *= f;
            Ps[(wr + i) * PAD + lane]      = p0;
            Ps[(wr + i) * PAD + lane + 32] = p1;
        }
        __syncwarp();   // Ps rows [wr, wr+8) are warp-private

        // O += P @ V : P read as float4 over kk (broadcast), V scalar contiguous
#pragma unroll 4
        for (int kk = 0; kk < 64; kk += 4) {
            float va0 = Vs[(kk + 0) * PAD + r0];
            float va1 = Vs[(kk + 1) * PAD + r0];
            float va2 = Vs[(kk + 2) * PAD + r0];
            float va3 = Vs[(kk + 3) * PAD + r0];
            float vb0 = Vs[(kk + 0) * PAD + r1];
            float vb1 = Vs[(kk + 1) * PAD + r1];
            float vb2 = Vs[(kk + 2) * PAD + r1];
            float vb3 = Vs[(kk + 3) * PAD + r1];
#pragma unroll
            for (int i = 0; i < 8; i++) {
                float4 p = *(const float4*)&Ps[(wr + i) * PAD + kk];
                o0[i] += p.x * va0 + p.y * va1 + p.z * va2 + p.w * va3;
                o1[i] += p.x * vb0 + p.y * vb1 + p.z * vb2 + p.w * vb3;
            }
        }
    }

    // Epilogue: normalize, write context
#pragma unroll
    for (int i = 0; i < 8; i++) {
        float inv = 1.0f / lrow[i];
        float* orow = O + base + (size_t)(q0 + wr + i) * EDIM;
        orow[r0] = o0[i] * inv;
        orow[r1] = o1[i] * inv;
    }
}

// ---------------------------------------------------------------------------
// Launch: 3 QKV GEMMs -> attention -> output GEMM. All graph-capturable.
// ---------------------------------------------------------------------------
extern "C" void kernel_launch(void* const* d_in, const int* in_sizes, int n_in,
                              void* d_out, int out_size)
{
    const float* x  = (const float*)d_in[0];
    const float* Wq = (const float*)d_in[1];
    const float* bq = (const float*)d_in[2];
    const float* Wk = (const float*)d_in[3];
    const float* bk = (const float*)d_in[4];
    const float* Wv = (const float*)d_in[5];
    const float* bv = (const float*)d_in[6];
    const float* Wo = (const float*)d_in[7];
    const float* bo = (const float*)d_in[8];
    float* out = (float*)d_out;

    float *qp, *kp, *vp, *cp;
    cudaGetSymbolAddress((void**)&qp, g_Q);
    cudaGetSymbolAddress((void**)&kp, g_K);
    cudaGetSymbolAddress((void**)&vp, g_V);
    cudaGetSymbolAddress((void**)&cp, g_C);

    dim3 gg(EDIM / 128, MTOT / 128);   // (8, 32)
    sgemm_bias<<<gg, 256>>>(x, Wq, bq, qp);
    sgemm_bias<<<gg, 256>>>(x, Wk, bk, kp);
    sgemm_bias<<<gg, 256>>>(x, Wv, bv, vp);

    size_t smem = (size_t)4 * 64 * PAD * sizeof(float);   // 69632 B
    cudaFuncSetAttribute(attn_kernel, cudaFuncAttributeMaxDynamicSharedMemorySize, (int)smem);
    attn_kernel<<<dim3(SS / 64, BB * HEADS), 256, smem>>>(qp, kp, vp, cp);

    sgemm_bias<<<gg, 256>>>(cp, Wo, bo, out);
}

// round 11
// speedup vs baseline: 1.1120x; 1.0009x over previous
#include <cuda_runtime.h>
#include <math.h>
#include <float.h>

#define EDIM   1024
#define HEADS  16
#define DH     64
#define BB     2
#define SS     2048
#define MTOT   (BB * SS)      // 4096
#define PAD    68             // smem row pad (words): 16B-aligned, 17x16B odd stride -> conflict-free

// Scratch (allocation-free rule: __device__ globals)
__device__ float g_Q[MTOT * EDIM];
__device__ float g_K[MTOT * EDIM];
__device__ float g_V[MTOT * EDIM];
__device__ float g_C[MTOT * EDIM];

// ---------------------------------------------------------------------------
// SGEMM + bias: C[M,N] = A[M,K] @ B[K,N] + bias[N]
// Fixed K = N = 1024, M = 4096. 128x128x8 tile, 256 threads, 8x8 microtile.
// Double-buffered smem (1 sync/iter), float4 fragment reads.
// ---------------------------------------------------------------------------
__global__ __launch_bounds__(256) void sgemm_bias(
    const float* __restrict__ A, const float* __restrict__ B,
    const float* __restrict__ bias, float* __restrict__ C)
{
    const int K = EDIM, N = EDIM;
    __shared__ float As[2][8][128];   // transposed A tile: As[buf][k][m]
    __shared__ float Bs[2][8][128];   // Bs[buf][k][n]

    const int tid = threadIdx.x;
    const int bm  = blockIdx.y * 128;
    const int bn  = blockIdx.x * 128;
    const int tx  = tid & 15;      // 0..15  -> n microtile
    const int ty  = tid >> 4;      // 0..15  -> m microtile

    const int a_row = tid >> 1;          // 0..127
    const int a_col = (tid & 1) * 4;     // 0 or 4
    const int b_row = tid >> 5;          // 0..7
    const int b_col = (tid & 31) * 4;    // 0..124

    const float* Aptr = A + (size_t)(bm + a_row) * K + a_col;
    const float* Bptr = B + (size_t)b_row * N + bn + b_col;

    float acc[8][8];
#pragma unroll
    for (int i = 0; i < 8; i++)
#pragma unroll
        for (int j = 0; j < 8; j++) acc[i][j] = 0.f;

    // Prologue: fill buffer 0
    {
        float4 av = *(const float4*)(Aptr);
        float4 bv = *(const float4*)(Bptr);
        As[0][a_col + 0][a_row] = av.x;
        As[0][a_col + 1][a_row] = av.y;
        As[0][a_col + 2][a_row] = av.z;
        As[0][a_col + 3][a_row] = av.w;
        *(float4*)&Bs[0][b_row][b_col] = bv;
    }
    __syncthreads();

    int cur = 0;
    for (int k0 = 0; k0 < K; k0 += 8) {
        const bool has_next = (k0 + 8) < K;
        float4 av, bv;
        if (has_next) {
            av = *(const float4*)(Aptr + (k0 + 8));
            bv = *(const float4*)(Bptr + (size_t)(k0 + 8) * N);
        }

#pragma unroll
        for (int k = 0; k < 8; k++) {
            float4 a0 = *(const float4*)&As[cur][k][ty * 8];
            float4 a1 = *(const float4*)&As[cur][k][ty * 8 + 4];
            float4 b0 = *(const float4*)&Bs[cur][k][tx * 8];
            float4 b1 = *(const float4*)&Bs[cur][k][tx * 8 + 4];
            float ar[8] = {a0.x, a0.y, a0.z, a0.w, a1.x, a1.y, a1.z, a1.w};
            float br[8] = {b0.x, b0.y, b0.z, b0.w, b1.x, b1.y, b1.z, b1.w};
#pragma unroll
            for (int i = 0; i < 8; i++)
#pragma unroll
                for (int j = 0; j < 8; j++) acc[i][j] += ar[i] * br[j];
        }

        if (has_next) {
            const int nxt = cur ^ 1;
            As[nxt][a_col + 0][a_row] = av.x;
            As[nxt][a_col + 1][a_row] = av.y;
            As[nxt][a_col + 2][a_row] = av.z;
            As[nxt][a_col + 3][a_row] = av.w;
            *(float4*)&Bs[nxt][b_row][b_col] = bv;
            __syncthreads();
            cur = nxt;
        }
    }

    // Epilogue: + bias, vectorized stores
    const int cn = bn + tx * 8;
    float4 bias0 = *(const float4*)&bias[cn];
    float4 bias1 = *(const float4*)&bias[cn + 4];
#pragma unroll
    for (int i = 0; i < 8; i++) {
        float* crow = C + (size_t)(bm + ty * 8 + i) * N + cn;
        float4 v0 = make_float4(acc[i][0] + bias0.x, acc[i][1] + bias0.y,
                                acc[i][2] + bias0.z, acc[i][3] + bias0.w);
        float4 v1 = make_float4(acc[i][4] + bias1.x, acc[i][5] + bias1.y,
                                acc[i][6] + bias1.z, acc[i][7] + bias1.w);
        *(float4*)crow       = v0;
        *(float4*)(crow + 4) = v1;
    }
}

// ---------------------------------------------------------------------------
// Flash attention (fp32, online softmax), float4 smem reads everywhere.
// Grid: (S/64, B*H), 256 threads (8 warps). Warp w owns query rows [8w, 8w+8);
// lane owns head-dim / key columns {lane, lane+32}.
// ---------------------------------------------------------------------------
__global__ __launch_bounds__(256) void attn_kernel(
    const float* __restrict__ Q, const float* __restrict__ Kg,
    const float* __restrict__ Vg, float* __restrict__ O)
{
    extern __shared__ float sm[];
    float* Qs = sm;                 // 64 x PAD  (rows = query,  cols = dh)
    float* Ks = sm + 64 * PAD;      // 64 x PAD  (rows = key,    cols = dh)
    float* Vs = sm + 2 * 64 * PAD;  // 64 x PAD  (rows = key,    cols = dh)
    float* Ps = sm + 3 * 64 * PAD;  // 64 x PAD  (rows = query,  cols = key)

    const int tid  = threadIdx.x;
    const int lane = tid & 31;
    const int warp = tid >> 5;
    const int qt   = blockIdx.x;          // query tile 0..31
    const int bh   = blockIdx.y;          // 0..31
    const int b    = bh >> 4;
    const int h    = bh & 15;
    const int q0   = qt * 64;
    const size_t base = (size_t)b * SS * EDIM + (size_t)h * DH;

    // Load Q tile (64 x 64)
    for (int i = tid; i < 64 * 16; i += 256) {       // 1024 float4 slots
        int r = i >> 4;
        int c = (i & 15) * 4;
        float4 v = *(const float4*)&Q[base + (size_t)(q0 + r) * EDIM + c];
        *(float4*)&Qs[r * PAD + c] = v;
    }

    float o0[8], o1[8], mrow[8], lrow[8];
#pragma unroll
    for (int i = 0; i < 8; i++) { o0[i] = 0.f; o1[i] = 0.f; mrow[i] = -FLT_MAX; lrow[i] = 0.f; }
    const int wr = warp * 8;
    const int r0 = lane;            // this lane's key/dh column 0
    const int r1 = lane + 32;       // this lane's key/dh column 1

    for (int kt = 0; kt < SS / 64; kt++) {
        __syncthreads();   // previous iteration's Ks/Vs/Ps reads done (also covers Qs on kt=0)
        const int k0 = kt * 64;
        for (int i = tid; i < 64 * 16; i += 256) {
            int r = i >> 4;
            int c = (i & 15) * 4;
            size_t g = base + (size_t)(k0 + r) * EDIM + c;
            float4 kv = *(const float4*)&Kg[g];
            float4 vv = *(const float4*)&Vg[g];
            *(float4*)&Ks[r * PAD + c] = kv;
            *(float4*)&Vs[r * PAD + c] = vv;
        }
        __syncthreads();

        // Scores: s[r][c] = dot(Q[r], K[c]) ; lane cols c0=lane, c1=lane+32
        float s0[8], s1[8];
#pragma unroll
        for (int i = 0; i < 8; i++) { s0[i] = 0.f; s1[i] = 0.f; }
#pragma unroll 4
        for (int kk = 0; kk < 64; kk += 4) {
            float4 k0v = *(const float4*)&Ks[r0 * PAD + kk];
            float4 k1v = *(const float4*)&Ks[r1 * PAD + kk];
#pragma unroll
            for (int i = 0; i < 8; i++) {
                float4 qv = *(const float4*)&Qs[(wr + i) * PAD + kk];
                s0[i] += qv.x * k0v.x + qv.y * k0v.y + qv.z * k0v.z + qv.w * k0v.w;
                s1[i] += qv.x * k1v.x + qv.y * k1v.y + qv.z * k1v.z + qv.w * k1v.w;
            }
        }

        // Online softmax (per row, warp-wide)
        const float sc = 0.125f;   // 1/sqrt(64)
#pragma unroll
        for (int i = 0; i < 8; i++) {
            s0[i] *= sc; s1[i] *= sc;
            float v = fmaxf(s0[i], s1[i]);
#pragma unroll
            for (int off = 16; off > 0; off >>= 1)
                v = fmaxf(v, __shfl_xor_sync(0xffffffffu, v, off));
            float mn = fmaxf(mrow[i], v);
            float f  = __expf(mrow[i] - mn);
            float p0 = __expf(s0[i] - mn);
            float p1 = __expf(s1[i] - mn);
            float rs = p0 + p1;
#pragma unroll
            for (int off = 16; off > 0; off >>= 1)
                rs += __shfl_xor_sync(0xffffffffu, rs, off);
            lrow[i] = lrow[i] * f + rs;
            mrow[i] = mn;
            o0[i] *= f; o1[i] *= f;
            Ps[(wr + i) * PAD + lane]      = p0;
            Ps[(wr + i) * PAD + lane + 32] = p1;
        }
        __syncwarp();   // Ps rows [wr, wr+8) are warp-private

        // O += P @ V : P read as float4 over kk (broadcast), V scalar contiguous
#pragma unroll 4
        for (int kk = 0; kk < 64; kk += 4) {
            float va0 = Vs[(kk + 0) * PAD + r0];
            float va1 = Vs[(kk + 1) * PAD + r0];
            float va2 = Vs[(kk + 2) * PAD + r0];
            float va3 = Vs[(kk + 3) * PAD + r0];
            float vb0 = Vs[(kk + 0) * PAD + r1];
            float vb1 = Vs[(kk + 1) * PAD + r1];
            float vb2 = Vs[(kk + 2) * PAD + r1];
            float vb3 = Vs[(kk + 3) * PAD + r1];
#pragma unroll
            for (int i = 0; i < 8; i++) {
                float4 p = *(const float4*)&Ps[(wr + i) * PAD + kk];
                o0[i] += p.x * va0 + p.y * va1 + p.z * va2 + p.w * va3;
                o1[i] += p.x * vb0 + p.y * vb1 + p.z * vb2 + p.w * vb3;
            }
        }
    }

    // Epilogue: normalize, write context
#pragma unroll
    for (int i = 0; i < 8; i++) {
        float inv = 1.0f / lrow[i];
        float* orow = O + base + (size_t)(q0 + wr + i) * EDIM;
        orow[r0] = o0[i] * inv;
        orow[r1] = o1[i] * inv;
    }
}

// ---------------------------------------------------------------------------
// Launch: 3 QKV GEMMs -> attention -> output GEMM. All graph-capturable.
// ---------------------------------------------------------------------------
extern "C" void kernel_launch(void* const* d_in, const int* in_sizes, int n_in,
                              void* d_out, int out_size)
{
    const float* x  = (const float*)d_in[0];
    const float* Wq = (const float*)d_in[1];
    const float* bq = (const float*)d_in[2];
    const float* Wk = (const float*)d_in[3];
    const float* bk = (const float*)d_in[4];
    const float* Wv = (const float*)d_in[5];
    const float* bv = (const float*)d_in[6];
    const float* Wo = (const float*)d_in[7];
    const float* bo = (const float*)d_in[8];
    float* out = (float*)d_out;

    float *qp, *kp, *vp, *cp;
    cudaGetSymbolAddress((void**)&qp, g_Q);
    cudaGetSymbolAddress((void**)&kp, g_K);
    cudaGetSymbolAddress((void**)&vp, g_V);
    cudaGetSymbolAddress((void**)&cp, g_C);

    dim3 gg(EDIM / 128, MTOT / 128);   // (8, 32)
    sgemm_bias<<<gg, 256>>>(x, Wq, bq, qp);
    sgemm_bias<<<gg, 256>>>(x, Wk, bk, kp);
    sgemm_bias<<<gg, 256>>>(x, Wv, bv, vp);

    size_t smem = (size_t)4 * 64 * PAD * sizeof(float);   // 69632 B
    cudaFuncSetAttribute(attn_kernel, cudaFuncAttributeMaxDynamicSharedMemorySize, (int)smem);
    attn_kernel<<<dim3(SS / 64, BB * HEADS), 256, smem>>>(qp, kp, vp, cp);

    sgemm_bias<<<gg, 256>>>(cp, Wo, bo, out);
}

// round 14
// speedup vs baseline: 1.4635x; 1.3161x over previous
#include <cuda_runtime.h>
#include <cuda_bf16.h>
#include <math.h>
#include <float.h>
#include <stdint.h>

#define EDIM   1024
#define HEADS  16
#define DH     64
#define BB     2
#define SS     2048
#define MTOT   (BB * SS)      // 4096
#define PAD    68             // attention smem pad

// ---------------- scratch (__device__ globals; no allocs allowed) ----------
__device__ float g_Q[MTOT * EDIM];
__device__ float g_K[MTOT * EDIM];
__device__ float g_V[MTOT * EDIM];
__device__ float g_C[MTOT * EDIM];

__device__ __nv_bfloat16 g_xh[MTOT * EDIM], g_xl[MTOT * EDIM];
__device__ __nv_bfloat16 g_ch[MTOT * EDIM], g_cl[MTOT * EDIM];
__device__ __nv_bfloat16 g_Wqh[EDIM * EDIM], g_Wql[EDIM * EDIM];
__device__ __nv_bfloat16 g_Wkh[EDIM * EDIM], g_Wkl[EDIM * EDIM];
__device__ __nv_bfloat16 g_Wvh[EDIM * EDIM], g_Wvl[EDIM * EDIM];
__device__ __nv_bfloat16 g_Woh[EDIM * EDIM], g_Wol[EDIM * EDIM];

// ---------------- helpers ---------------------------------------------------
__device__ __forceinline__ uint32_t smem_u32(const void* p) {
    return (uint32_t)__cvta_generic_to_shared(p);
}

__device__ __forceinline__ void ldsm4(uint32_t addr, uint32_t& r0, uint32_t& r1,
                                      uint32_t& r2, uint32_t& r3) {
    asm volatile("ldmatrix.sync.aligned.m8n8.x4.shared.b16 {%0,%1,%2,%3}, [%4];"
                 : "=r"(r0), "=r"(r1), "=r"(r2), "=r"(r3) : "r"(addr));
}

__device__ __forceinline__ void mma16816(float* c, const uint32_t* a,
                                         uint32_t b0, uint32_t b1) {
    asm volatile(
        "mma.sync.aligned.m16n8k16.row.col.f32.bf16.bf16.f32 "
        "{%0,%1,%2,%3}, {%4,%5,%6,%7}, {%8,%9}, {%0,%1,%2,%3};"
        : "+f"(c[0]), "+f"(c[1]), "+f"(c[2]), "+f"(c[3])
        : "r"(a[0]), "r"(a[1]), "r"(a[2]), "r"(a[3]), "r"(b0), "r"(b1));
}

__device__ __forceinline__ uint32_t sw128(uint32_t off) {
    return off ^ ((off >> 3) & 0x70);
}

// ---------------------------------------------------------------------------
// Split fp32 -> bf16 hi/lo (elementwise, float4 granularity)
// ---------------------------------------------------------------------------
__global__ void xsplit(const float4* __restrict__ in,
                       __nv_bfloat162* __restrict__ h, __nv_bfloat162* __restrict__ l, int n4)
{
    int i = blockIdx.x * blockDim.x + threadIdx.x;
    if (i >= n4) return;
    float4 v = in[i];
    __nv_bfloat16 hx = __float2bfloat16_rn(v.x);
    __nv_bfloat16 hy = __float2bfloat16_rn(v.y);
    __nv_bfloat16 hz = __float2bfloat16_rn(v.z);
    __nv_bfloat16 hw = __float2bfloat16_rn(v.w);
    __nv_bfloat16 lx = __float2bfloat16_rn(v.x - __bfloat162float(hx));
    __nv_bfloat16 ly = __float2bfloat16_rn(v.y - __bfloat162float(hy));
    __nv_bfloat16 lz = __float2bfloat16_rn(v.z - __bfloat162float(hz));
    __nv_bfloat16 lw = __float2bfloat16_rn(v.w - __bfloat162float(hw));
    h[2 * i]     = __nv_bfloat162(hx, hy);
    h[2 * i + 1] = __nv_bfloat162(hz, hw);
    l[2 * i]     = __nv_bfloat162(lx, ly);
    l[2 * i + 1] = __nv_bfloat162(lz, lw);
}

// ---------------------------------------------------------------------------
// Transpose + split: W[k][n] (1024x1024 fp32) -> Th/Tl[n][k] bf16
// ---------------------------------------------------------------------------
__global__ void wsplit_t(const float* __restrict__ W,
                         __nv_bfloat16* __restrict__ Th, __nv_bfloat16* __restrict__ Tl)
{
    __shared__ float t[32][33];
    const int n0 = blockIdx.x * 32, k0 = blockIdx.y * 32;
    const int x = threadIdx.x, y = threadIdx.y;   // 32 x 8
#pragma unroll
    for (int i = y; i < 32; i += 8)
        t[i][x] = W[(size_t)(k0 + i) * EDIM + n0 + x];
    __syncthreads();
#pragma unroll
    for (int i = y; i < 32; i += 8) {
        float v = t[x][i];   // = W[k0+x][n0+i]
        __nv_bfloat16 hv = __float2bfloat16_rn(v);
        __nv_bfloat16 lv = __float2bfloat16_rn(v - __bfloat162float(hv));
        size_t o = (size_t)(n0 + i) * EDIM + k0 + x;
        Th[o] = hv;
        Tl[o] = lv;
    }
}

// ---------------------------------------------------------------------------
// HMMA bf16x3 GEMM + bias: C[M,N] = (Ah+Al)[M,K] @ (Bh+Bl)^T + bias
// A: [M,K] bf16 row-major; B: [N,K] bf16 row-major (transposed weights).
// CTA tile 128x128, 8 warps (2m x 4n), warp tile 64x32.
// K in chunks of 64 staged in SW128-swizzled smem (Ah/Al/Bh/Bl = 64KB).
// Grid (N/128, M/128) = (8, 32), 256 threads.
// ---------------------------------------------------------------------------
#define GEMM_SMEM (4 * 16384 + 1024)

__global__ __launch_bounds__(256) void hmma_gemm_bias(
    const __nv_bfloat16* __restrict__ Ah, const __nv_bfloat16* __restrict__ Al,
    const __nv_bfloat16* __restrict__ Bh, const __nv_bfloat16* __restrict__ Bl,
    const float* __restrict__ bias, float* __restrict__ C)
{
    extern __shared__ char smem[];
    const uint32_t sbase = (smem_u32(smem) + 1023) & ~1023u;
    const uint32_t sAh = sbase;
    const uint32_t sAl = sbase + 16384;
    const uint32_t sBh = sbase + 2 * 16384;
    const uint32_t sBl = sbase + 3 * 16384;

    const int tid  = threadIdx.x;
    const int wid  = tid >> 5;
    const int lane = tid & 31;
    const int wm   = wid >> 2;          // 0..1  -> m offset wm*64
    const int wn   = wid & 3;           // 0..3  -> n offset wn*32
    const int m0   = blockIdx.y * 128;
    const int n0   = blockIdx.x * 128;

    const uint4* gAh = (const uint4*)Ah;
    const uint4* gAl = (const uint4*)Al;
    const uint4* gBh = (const uint4*)Bh;
    const uint4* gBl = (const uint4*)Bl;

    // ldmatrix per-lane source coordinates (within tile)
    const int a_row = lane & 15;              // + wm*64 + mf*16
    const int a_kb  = (lane >> 4) * 16;       // + s*32
    const int b_row = (lane & 7) | ((lane & 16) >> 1);   // + wn*32 + nb*16
    const int b_kb  = (lane & 8) * 2;         // + s*32

    float acc[4][4][4];
#pragma unroll
    for (int i = 0; i < 4; i++)
#pragma unroll
        for (int j = 0; j < 4; j++)
#pragma unroll
            for (int r = 0; r < 4; r++) acc[i][j][r] = 0.f;

    for (int kc = 0; kc < 16; kc++) {
        // stage 128x64 bf16 tiles: 1024 uint4 per tile, 4 per thread per tile
#pragma unroll
        for (int t = 0; t < 4; t++) {
            const int idx = tid + t * 256;         // 0..1023
            const int row = idx >> 3;              // 0..127
            const int c16 = idx & 7;               // 16B unit in row
            const uint32_t sw = sw128((uint32_t)(row * 128 + c16 * 16));
            const int ga = (m0 + row) * 128 + kc * 8 + c16;
            const int gb = (n0 + row) * 128 + kc * 8 + c16;
            uint4 va = gAh[ga];
            uint4 vb = gAl[ga];
            uint4 vc = gBh[gb];
            uint4 vd = gBl[gb];
            asm volatile("st.shared.v4.b32 [%0], {%1,%2,%3,%4};" ::
                "r"(sAh + sw), "r"(va.x), "r"(va.y), "r"(va.z), "r"(va.w) : "memory");
            asm volatile("st.shared.v4.b32 [%0], {%1,%2,%3,%4};" ::
                "r"(sAl + sw), "r"(vb.x), "r"(vb.y), "r"(vb.z), "r"(vb.w) : "memory");
            asm volatile("st.shared.v4.b32 [%0], {%1,%2,%3,%4};" ::
                "r"(sBh + sw), "r"(vc.x), "r"(vc.y), "r"(vc.z), "r"(vc.w) : "memory");
            asm volatile("st.shared.v4.b32 [%0], {%1,%2,%3,%4};" ::
                "r"(sBl + sw), "r"(vd.x), "r"(vd.y), "r"(vd.z), "r"(vd.w) : "memory");
        }
        __syncthreads();

#pragma unroll
        for (int s = 0; s < 4; s++) {
            const int kb = s * 32;
            uint32_t ah[16], al[16], bh[8], bl[8];
#pragma unroll
            for (int mf = 0; mf < 4; mf++) {
                const uint32_t off = (uint32_t)((wm * 64 + mf * 16 + a_row) * 128 + a_kb + kb);
                const uint32_t sw = sw128(off);
                ldsm4(sAh + sw, ah[mf * 4], ah[mf * 4 + 1], ah[mf * 4 + 2], ah[mf * 4 + 3]);
                ldsm4(sAl + sw, al[mf * 4], al[mf * 4 + 1], al[mf * 4 + 2], al[mf * 4 + 3]);
            }
#pragma unroll
            for (int nb = 0; nb < 2; nb++) {
                const uint32_t off = (uint32_t)((wn * 32 + nb * 16 + b_row) * 128 + b_kb + kb);
                const uint32_t sw = sw128(off);
                ldsm4(sBh + sw, bh[nb * 4], bh[nb * 4 + 1], bh[nb * 4 + 2], bh[nb * 4 + 3]);
                ldsm4(sBl + sw, bl[nb * 4], bl[nb * 4 + 1], bl[nb * 4 + 2], bl[nb * 4 + 3]);
            }
#pragma unroll
            for (int mf = 0; mf < 4; mf++)
#pragma unroll
                for (int nf = 0; nf < 4; nf++) {
                    mma16816(acc[mf][nf], &ah[mf * 4], bh[nf * 2], bh[nf * 2 + 1]);
                    mma16816(acc[mf][nf], &ah[mf * 4], bl[nf * 2], bl[nf * 2 + 1]);
                    mma16816(acc[mf][nf], &al[mf * 4], bh[nf * 2], bh[nf * 2 + 1]);
                }
        }
        __syncthreads();
    }

    // Epilogue: fragment (m16n8) lane mapping: rows = l>>2 (+8), cols = (l&3)*2
    const int er = lane >> 2;
    const int ec = (lane & 3) * 2;
#pragma unroll
    for (int mf = 0; mf < 4; mf++) {
#pragma unroll
        for (int nf = 0; nf < 4; nf++) {
            const int col = n0 + wn * 32 + nf * 8 + ec;
            const float b0 = bias[col], b1 = bias[col + 1];
            const int row0 = m0 + wm * 64 + mf * 16 + er;
            float2 v0 = make_float2(acc[mf][nf][0] + b0, acc[mf][nf][1] + b1);
            float2 v1 = make_float2(acc[mf][nf][2] + b0, acc[mf][nf][3] + b1);
            *(float2*)&C[(size_t)row0 * EDIM + col]       = v0;
            *(float2*)&C[(size_t)(row0 + 8) * EDIM + col] = v1;
        }
    }
}

// ---------------------------------------------------------------------------
// Flash attention (fp32, online softmax) — unchanged (known good)
// ---------------------------------------------------------------------------
__global__ __launch_bounds__(256) void attn_kernel(
    const float* __restrict__ Q, const float* __restrict__ Kg,
    const float* __restrict__ Vg, float* __restrict__ O)
{
    extern __shared__ float sm[];
    float* Qs = sm;
    float* Ks = sm + 64 * PAD;
    float* Vs = sm + 2 * 64 * PAD;
    float* Ps = sm + 3 * 64 * PAD;

    const int tid  = threadIdx.x;
    const int lane = tid & 31;
    const int warp = tid >> 5;
    const int qt   = blockIdx.x;
    const int bh   = blockIdx.y;
    const int b    = bh >> 4;
    const int h    = bh & 15;
    const int q0   = qt * 64;
    const size_t base = (size_t)b * SS * EDIM + (size_t)h * DH;

    for (int i = tid; i < 64 * 16; i += 256) {
        int r = i >> 4;
        int c = (i & 15) * 4;
        float4 v = *(const float4*)&Q[base + (size_t)(q0 + r) * EDIM + c];
        *(float4*)&Qs[r * PAD + c] = v;
    }

    float o0[8], o1[8], mrow[8], lrow[8];
#pragma unroll
    for (int i = 0; i < 8; i++) { o0[i] = 0.f; o1[i] = 0.f; mrow[i] = -FLT_MAX; lrow[i] = 0.f; }
    const int wr = warp * 8;
    const int r0 = lane;
    const int r1 = lane + 32;

    for (int kt = 0; kt < SS / 64; kt++) {
        __syncthreads();
        const int k0 = kt * 64;
        for (int i = tid; i < 64 * 16; i += 256) {
            int r = i >> 4;
            int c = (i & 15) * 4;
            size_t g = base + (size_t)(k0 + r) * EDIM + c;
            float4 kv = *(const float4*)&Kg[g];
            float4 vv = *(const float4*)&Vg[g];
            *(float4*)&Ks[r * PAD + c] = kv;
            *(float4*)&Vs[r * PAD + c] = vv;
        }
        __syncthreads();

        float s0[8], s1[8];
#pragma unroll
        for (int i = 0; i < 8; i++) { s0[i] = 0.f; s1[i] = 0.f; }
#pragma unroll 4
        for (int kk = 0; kk < 64; kk += 4) {
            float4 k0v = *(const float4*)&Ks[r0 * PAD + kk];
            float4 k1v = *(const float4*)&Ks[r1 * PAD + kk];
#pragma unroll
            for (int i = 0; i < 8; i++) {
                float4 qv = *(const float4*)&Qs[(wr + i) * PAD + kk];
                s0[i] += qv.x * k0v.x + qv.y * k0v.y + qv.z * k0v.z + qv.w * k0v.w;
                s1[i] += qv.x * k1v.x + qv.y * k1v.y + qv.z * k1v.z + qv.w * k1v.w;
            }
        }

        const float sc = 0.125f;
#pragma unroll
        for (int i = 0; i < 8; i++) {
            s0[i] *= sc; s1[i] *= sc;
            float v = fmaxf(s0[i], s1[i]);
#pragma unroll
            for (int off = 16; off > 0; off >>= 1)
                v = fmaxf(v, __shfl_xor_sync(0xffffffffu, v, off));
            float mn = fmaxf(mrow[i], v);
            float f  = __expf(mrow[i] - mn);
            float p0 = __expf(s0[i] - mn);
            float p1 = __expf(s1[i] - mn);
            float rs = p0 + p1;
#pragma unroll
            for (int off = 16; off > 0; off >>= 1)
                rs += __shfl_xor_sync(0xffffffffu, rs, off);
            lrow[i] = lrow[i] * f + rs;
            mrow[i] = mn;
            o0[i] *= f; o1[i] *= f;
            Ps[(wr + i) * PAD + lane]      = p0;
            Ps[(wr + i) * PAD + lane + 32] = p1;
        }
        __syncwarp();

#pragma unroll 4
        for (int kk = 0; kk < 64; kk += 4) {
            float va0 = Vs[(kk + 0) * PAD + r0];
            float va1 = Vs[(kk + 1) * PAD + r0];
            float va2 = Vs[(kk + 2) * PAD + r0];
            float va3 = Vs[(kk + 3) * PAD + r0];
            float vb0 = Vs[(kk + 0) * PAD + r1];
            float vb1 = Vs[(kk + 1) * PAD + r1];
            float vb2 = Vs[(kk + 2) * PAD + r1];
            float vb3 = Vs[(kk + 3) * PAD + r1];
#pragma unroll
            for (int i = 0; i < 8; i++) {
                float4 p = *(const float4*)&Ps[(wr + i) * PAD + kk];
                o0[i] += p.x * va0 + p.y * va1 + p.z * va2 + p.w * va3;
                o1[i] += p.x * vb0 + p.y * vb1 + p.z * vb2 + p.w * vb3;
            }
        }
    }

#pragma unroll
    for (int i = 0; i < 8; i++) {
        float inv = 1.0f / lrow[i];
        float* orow = O + base + (size_t)(q0 + wr + i) * EDIM;
        orow[r0] = o0[i] * inv;
        orow[r1] = o1[i] * inv;
    }
}

// ---------------------------------------------------------------------------
// Launch sequence (graph-capturable, no allocs)
// ---------------------------------------------------------------------------
extern "C" void kernel_launch(void* const* d_in, const int* in_sizes, int n_in,
                              void* d_out, int out_size)
{
    const float* x  = (const float*)d_in[0];
    const float* Wq = (const float*)d_in[1];
    const float* bq = (const float*)d_in[2];
    const float* Wk = (const float*)d_in[3];
    const float* bk = (const float*)d_in[4];
    const float* Wv = (const float*)d_in[5];
    const float* bv = (const float*)d_in[6];
    const float* Wo = (const float*)d_in[7];
    const float* bo = (const float*)d_in[8];
    float* out = (float*)d_out;

    float *qp, *kp, *vp, *cp;
    cudaGetSymbolAddress((void**)&qp, g_Q);
    cudaGetSymbolAddress((void**)&kp, g_K);
    cudaGetSymbolAddress((void**)&vp, g_V);
    cudaGetSymbolAddress((void**)&cp, g_C);
    __nv_bfloat16 *xh, *xl, *ch, *cl, *wqh, *wql, *wkh, *wkl, *wvh, *wvl, *woh, *wol;
    cudaGetSymbolAddress((void**)&xh, g_xh);  cudaGetSymbolAddress((void**)&xl, g_xl);
    cudaGetSymbolAddress((void**)&ch, g_ch);  cudaGetSymbolAddress((void**)&cl, g_cl);
    cudaGetSymbolAddress((void**)&wqh, g_Wqh); cudaGetSymbolAddress((void**)&wql, g_Wql);
    cudaGetSymbolAddress((void**)&wkh, g_Wkh); cudaGetSymbolAddress((void**)&wkl, g_Wkl);
    cudaGetSymbolAddress((void**)&wvh, g_Wvh); cudaGetSymbolAddress((void**)&wvl, g_Wvl);
    cudaGetSymbolAddress((void**)&woh, g_Woh); cudaGetSymbolAddress((void**)&wol, g_Wol);

    // 1) split x into bf16 hi/lo; transpose+split weights
    const int n4 = MTOT * EDIM / 4;
    xsplit<<<(n4 + 255) / 256, 256>>>((const float4*)x,
        (__nv_bfloat162*)xh, (__nv_bfloat162*)xl, n4);
    dim3 wt(32, 8), wg(EDIM / 32, EDIM / 32);
    wsplit_t<<<wg, wt>>>(Wq, wqh, wql);
    wsplit_t<<<wg, wt>>>(Wk, wkh, wkl);
    wsplit_t<<<wg, wt>>>(Wv, wvh, wvl);
    wsplit_t<<<wg, wt>>>(Wo, woh, wol);

    static int smem_set = 0;
    if (!smem_set) {
        cudaFuncSetAttribute(hmma_gemm_bias, cudaFuncAttributeMaxDynamicSharedMemorySize, GEMM_SMEM);
        cudaFuncSetAttribute(attn_kernel, cudaFuncAttributeMaxDynamicSharedMemorySize,
                             (int)(4 * 64 * PAD * sizeof(float)));
        smem_set = 1;
    }

    // 2) QKV projections on tensor cores (HMMA bf16x3)
    dim3 gg(EDIM / 128, MTOT / 128);   // (8, 32)
    hmma_gemm_bias<<<gg, 256, GEMM_SMEM>>>(xh, xl, wqh, wql, bq, qp);
    hmma_gemm_bias<<<gg, 256, GEMM_SMEM>>>(xh, xl, wkh, wkl, bk, kp);
    hmma_gemm_bias<<<gg, 256, GEMM_SMEM>>>(xh, xl, wvh, wvl, bv, vp);

    // 3) attention (fp32)
    size_t smem = (size_t)4 * 64 * PAD * sizeof(float);
    attn_kernel<<<dim3(SS / 64, BB * HEADS), 256, smem>>>(qp, kp, vp, cp);

    // 4) output projection on tensor cores
    xsplit<<<(n4 + 255) / 256, 256>>>((const float4*)cp,
        (__nv_bfloat162*)ch, (__nv_bfloat162*)cl, n4);
    hmma_gemm_bias<<<gg, 256, GEMM_SMEM>>>(ch, cl, woh, wol, bo, out);
}

// round 15
// speedup vs baseline: 2.6552x; 1.8142x over previous
#include <cuda_runtime.h>
#include <cuda_bf16.h>
#include <math.h>
#include <float.h>
#include <stdint.h>

#define EDIM   1024
#define HEADS  16
#define DH     64
#define BB     2
#define SS     2048
#define MTOT   (BB * SS)      // 4096

// ---------------- scratch (__device__ globals; no allocs allowed) ----------
__device__ __nv_bfloat16 g_xh[MTOT * EDIM], g_xl[MTOT * EDIM];
__device__ __nv_bfloat16 g_Qh[MTOT * EDIM], g_Ql[MTOT * EDIM];
__device__ __nv_bfloat16 g_Kh[MTOT * EDIM], g_Kl[MTOT * EDIM];
__device__ __nv_bfloat16 g_Vh[MTOT * EDIM], g_Vl[MTOT * EDIM];
__device__ __nv_bfloat16 g_ch[MTOT * EDIM], g_cl[MTOT * EDIM];
__device__ __nv_bfloat16 g_Wqh[EDIM * EDIM], g_Wql[EDIM * EDIM];
__device__ __nv_bfloat16 g_Wkh[EDIM * EDIM], g_Wkl[EDIM * EDIM];
__device__ __nv_bfloat16 g_Wvh[EDIM * EDIM], g_Wvl[EDIM * EDIM];
__device__ __nv_bfloat16 g_Woh[EDIM * EDIM], g_Wol[EDIM * EDIM];

// ---------------- helpers ---------------------------------------------------
__device__ __forceinline__ uint32_t smem_u32(const void* p) {
    return (uint32_t)__cvta_generic_to_shared(p);
}

__device__ __forceinline__ void ldsm4(uint32_t addr, uint32_t& r0, uint32_t& r1,
                                      uint32_t& r2, uint32_t& r3) {
    asm volatile("ldmatrix.sync.aligned.m8n8.x4.shared.b16 {%0,%1,%2,%3}, [%4];"
                 : "=r"(r0), "=r"(r1), "=r"(r2), "=r"(r3) : "r"(addr));
}

__device__ __forceinline__ void ldsm4t(uint32_t addr, uint32_t& r0, uint32_t& r1,
                                       uint32_t& r2, uint32_t& r3) {
    asm volatile("ldmatrix.sync.aligned.m8n8.x4.trans.shared.b16 {%0,%1,%2,%3}, [%4];"
                 : "=r"(r0), "=r"(r1), "=r"(r2), "=r"(r3) : "r"(addr));
}

__device__ __forceinline__ void mma16816(float* c, const uint32_t* a,
                                         uint32_t b0, uint32_t b1) {
    asm volatile(
        "mma.sync.aligned.m16n8k16.row.col.f32.bf16.bf16.f32 "
        "{%0,%1,%2,%3}, {%4,%5,%6,%7}, {%8,%9}, {%0,%1,%2,%3};"
        : "+f"(c[0]), "+f"(c[1]), "+f"(c[2]), "+f"(c[3])
        : "r"(a[0]), "r"(a[1]), "r"(a[2]), "r"(a[3]), "r"(b0), "r"(b1));
}

__device__ __forceinline__ uint32_t sw128(uint32_t off) {
    return off ^ ((off >> 3) & 0x70);
}

__device__ __forceinline__ uint32_t packbf(__nv_bfloat16 a, __nv_bfloat16 b) {
    __nv_bfloat162 t(a, b);          // x = a (low), y = b (high)
    return *(uint32_t*)&t;
}

// ---------------------------------------------------------------------------
// Split fp32 -> bf16 hi/lo (elementwise)
// ---------------------------------------------------------------------------
__global__ void xsplit(const float4* __restrict__ in,
                       __nv_bfloat162* __restrict__ h, __nv_bfloat162* __restrict__ l, int n4)
{
    int i = blockIdx.x * blockDim.x + threadIdx.x;
    if (i >= n4) return;
    float4 v = in[i];
    __nv_bfloat16 hx = __float2bfloat16_rn(v.x);
    __nv_bfloat16 hy = __float2bfloat16_rn(v.y);
    __nv_bfloat16 hz = __float2bfloat16_rn(v.z);
    __nv_bfloat16 hw = __float2bfloat16_rn(v.w);
    __nv_bfloat16 lx = __float2bfloat16_rn(v.x - __bfloat162float(hx));
    __nv_bfloat16 ly = __float2bfloat16_rn(v.y - __bfloat162float(hy));
    __nv_bfloat16 lz = __float2bfloat16_rn(v.z - __bfloat162float(hz));
    __nv_bfloat16 lw = __float2bfloat16_rn(v.w - __bfloat162float(hw));
    h[2 * i]     = __nv_bfloat162(hx, hy);
    h[2 * i + 1] = __nv_bfloat162(hz, hw);
    l[2 * i]     = __nv_bfloat162(lx, ly);
    l[2 * i + 1] = __nv_bfloat162(lz, lw);
}

// ---------------------------------------------------------------------------
// Transpose + split: W[k][n] (1024x1024 fp32) -> Th/Tl[n][k] bf16
// ---------------------------------------------------------------------------
__global__ void wsplit_t(const float* __restrict__ W,
                         __nv_bfloat16* __restrict__ Th, __nv_bfloat16* __restrict__ Tl)
{
    __shared__ float t[32][33];
    const int n0 = blockIdx.x * 32, k0 = blockIdx.y * 32;
    const int x = threadIdx.x, y = threadIdx.y;   // 32 x 8
#pragma unroll
    for (int i = y; i < 32; i += 8)
        t[i][x] = W[(size_t)(k0 + i) * EDIM + n0 + x];
    __syncthreads();
#pragma unroll
    for (int i = y; i < 32; i += 8) {
        float v = t[x][i];
        __nv_bfloat16 hv = __float2bfloat16_rn(v);
        __nv_bfloat16 lv = __float2bfloat16_rn(v - __bfloat162float(hv));
        size_t o = (size_t)(n0 + i) * EDIM + k0 + x;
        Th[o] = hv;
        Tl[o] = lv;
    }
}

// ---------------------------------------------------------------------------
// HMMA bf16x3 GEMM + bias. SPLIT=true: write bf16 hi/lo; else fp32.
// ---------------------------------------------------------------------------
#define GEMM_SMEM (4 * 16384 + 1024)

template <bool SPLIT>
__global__ __launch_bounds__(256) void hmma_gemm_bias(
    const __nv_bfloat16* __restrict__ Ah, const __nv_bfloat16* __restrict__ Al,
    const __nv_bfloat16* __restrict__ Bh, const __nv_bfloat16* __restrict__ Bl,
    const float* __restrict__ bias, float* __restrict__ C,
    __nv_bfloat16* __restrict__ Oh, __nv_bfloat16* __restrict__ Ol)
{
    extern __shared__ char smem[];
    const uint32_t sbase = (smem_u32(smem) + 1023) & ~1023u;
    const uint32_t sAh = sbase;
    const uint32_t sAl = sbase + 16384;
    const uint32_t sBh = sbase + 2 * 16384;
    const uint32_t sBl = sbase + 3 * 16384;

    const int tid  = threadIdx.x;
    const int wid  = tid >> 5;
    const int lane = tid & 31;
    const int wm   = wid >> 2;
    const int wn   = wid & 3;
    const int m0   = blockIdx.y * 128;
    const int n0   = blockIdx.x * 128;

    const uint4* gAh = (const uint4*)Ah;
    const uint4* gAl = (const uint4*)Al;
    const uint4* gBh = (const uint4*)Bh;
    const uint4* gBl = (const uint4*)Bl;

    const int a_row = lane & 15;
    const int a_kb  = (lane >> 4) * 16;
    const int b_row = (lane & 7) | ((lane & 16) >> 1);
    const int b_kb  = (lane & 8) * 2;

    float acc[4][4][4];
#pragma unroll
    for (int i = 0; i < 4; i++)
#pragma unroll
        for (int j = 0; j < 4; j++)
#pragma unroll
            for (int r = 0; r < 4; r++) acc[i][j][r] = 0.f;

    for (int kc = 0; kc < 16; kc++) {
#pragma unroll
        for (int t = 0; t < 4; t++) {
            const int idx = tid + t * 256;
            const int row = idx >> 3;
            const int c16 = idx & 7;
            const uint32_t sw = sw128((uint32_t)(row * 128 + c16 * 16));
            const int ga = (m0 + row) * 128 + kc * 8 + c16;
            const int gb = (n0 + row) * 128 + kc * 8 + c16;
            uint4 va = gAh[ga];
            uint4 vb = gAl[ga];
            uint4 vc = gBh[gb];
            uint4 vd = gBl[gb];
            asm volatile("st.shared.v4.b32 [%0], {%1,%2,%3,%4};" ::
                "r"(sAh + sw), "r"(va.x), "r"(va.y), "r"(va.z), "r"(va.w) : "memory");
            asm volatile("st.shared.v4.b32 [%0], {%1,%2,%3,%4};" ::
                "r"(sAl + sw), "r"(vb.x), "r"(vb.y), "r"(vb.z), "r"(vb.w) : "memory");
            asm volatile("st.shared.v4.b32 [%0], {%1,%2,%3,%4};" ::
                "r"(sBh + sw), "r"(vc.x), "r"(vc.y), "r"(vc.z), "r"(vc.w) : "memory");
            asm volatile("st.shared.v4.b32 [%0], {%1,%2,%3,%4};" ::
                "r"(sBl + sw), "r"(vd.x), "r"(vd.y), "r"(vd.z), "r"(vd.w) : "memory");
        }
        __syncthreads();

#pragma unroll
        for (int s = 0; s < 4; s++) {
            const int kb = s * 32;
            uint32_t ah[16], al[16], bh[8], bl[8];
#pragma unroll
            for (int mf = 0; mf < 4; mf++) {
                const uint32_t off = (uint32_t)((wm * 64 + mf * 16 + a_row) * 128 + a_kb + kb);
                const uint32_t sw = sw128(off);
                ldsm4(sAh + sw, ah[mf * 4], ah[mf * 4 + 1], ah[mf * 4 + 2], ah[mf * 4 + 3]);
                ldsm4(sAl + sw, al[mf * 4], al[mf * 4 + 1], al[mf * 4 + 2], al[mf * 4 + 3]);
            }
#pragma unroll
            for (int nb = 0; nb < 2; nb++) {
                const uint32_t off = (uint32_t)((wn * 32 + nb * 16 + b_row) * 128 + b_kb + kb);
                const uint32_t sw = sw128(off);
                ldsm4(sBh + sw, bh[nb * 4], bh[nb * 4 + 1], bh[nb * 4 + 2], bh[nb * 4 + 3]);
                ldsm4(sBl + sw, bl[nb * 4], bl[nb * 4 + 1], bl[nb * 4 + 2], bl[nb * 4 + 3]);
            }
#pragma unroll
            for (int mf = 0; mf < 4; mf++)
#pragma unroll
                for (int nf = 0; nf < 4; nf++) {
                    mma16816(acc[mf][nf], &ah[mf * 4], bh[nf * 2], bh[nf * 2 + 1]);
                    mma16816(acc[mf][nf], &ah[mf * 4], bl[nf * 2], bl[nf * 2 + 1]);
                    mma16816(acc[mf][nf], &al[mf * 4], bh[nf * 2], bh[nf * 2 + 1]);
                }
        }
        __syncthreads();
    }

    const int er = lane >> 2;
    const int ec = (lane & 3) * 2;
#pragma unroll
    for (int mf = 0; mf < 4; mf++) {
#pragma unroll
        for (int nf = 0; nf < 4; nf++) {
            const int col  = n0 + wn * 32 + nf * 8 + ec;
            const float b0 = bias[col], b1 = bias[col + 1];
            const int row0 = m0 + wm * 64 + mf * 16 + er;
            float v0 = acc[mf][nf][0] + b0, v1 = acc[mf][nf][1] + b1;
            float v2 = acc[mf][nf][2] + b0, v3 = acc[mf][nf][3] + b1;
            if (SPLIT) {
                __nv_bfloat16 h0 = __float2bfloat16_rn(v0);
                __nv_bfloat16 h1 = __float2bfloat16_rn(v1);
                __nv_bfloat16 h2 = __float2bfloat16_rn(v2);
                __nv_bfloat16 h3 = __float2bfloat16_rn(v3);
                __nv_bfloat16 l0 = __float2bfloat16_rn(v0 - __bfloat162float(h0));
                __nv_bfloat16 l1 = __float2bfloat16_rn(v1 - __bfloat162float(h1));
                __nv_bfloat16 l2 = __float2bfloat16_rn(v2 - __bfloat162float(h2));
                __nv_bfloat16 l3 = __float2bfloat16_rn(v3 - __bfloat162float(h3));
                *(__nv_bfloat162*)&Oh[(size_t)row0 * EDIM + col]       = __nv_bfloat162(h0, h1);
                *(__nv_bfloat162*)&Oh[(size_t)(row0 + 8) * EDIM + col] = __nv_bfloat162(h2, h3);
                *(__nv_bfloat162*)&Ol[(size_t)row0 * EDIM + col]       = __nv_bfloat162(l0, l1);
                *(__nv_bfloat162*)&Ol[(size_t)(row0 + 8) * EDIM + col] = __nv_bfloat162(l2, l3);
            } else {
                *(float2*)&C[(size_t)row0 * EDIM + col]       = make_float2(v0, v1);
                *(float2*)&C[(size_t)(row0 + 8) * EDIM + col] = make_float2(v2, v3);
            }
        }
    }
}

// ---------------------------------------------------------------------------
// HMMA flash attention, bf16 hi/lo compensated (3-term) QK^T and PV.
// CTA: 128 queries x one (b,h). 8 warps x 16 query rows. Key tile = 64.
// smem: 4 x 8KB buffers (Kh,Kl,Vh,Vl per tile; Qh/Ql staged there initially).
// ---------------------------------------------------------------------------
#define ATT_SMEM (4 * 8192 + 1024)

__global__ __launch_bounds__(256) void attn_hmma(
    const __nv_bfloat16* __restrict__ Qh_g, const __nv_bfloat16* __restrict__ Ql_g,
    const __nv_bfloat16* __restrict__ Kh_g, const __nv_bfloat16* __restrict__ Kl_g,
    const __nv_bfloat16* __restrict__ Vh_g, const __nv_bfloat16* __restrict__ Vl_g,
    __nv_bfloat16* __restrict__ Ch_g, __nv_bfloat16* __restrict__ Cl_g)
{
    extern __shared__ char smem[];
    const uint32_t sb = (smem_u32(smem) + 1023) & ~1023u;   // 4 x 8192B buffers

    const int tid  = threadIdx.x;
    const int lane = tid & 31;
    const int warp = tid >> 5;
    const int q0   = blockIdx.x * 128;
    const int bh   = blockIdx.y;
    const int b    = bh >> 4;
    const int h    = bh & 15;
    // uint4 index of (row, h*64): row*128 + h*8
    const int gbase = (b * SS) * 128 + h * 8;

    // ---- stage Q: hi rows 0-127 -> buf0/1, lo -> buf2/3
    {
        const uint4* qh4 = (const uint4*)Qh_g;
        const uint4* ql4 = (const uint4*)Ql_g;
#pragma unroll
        for (int t = 0; t < 8; t++) {
            const int idx  = tid + t * 256;      // 0..2047
            const int half = idx >> 10;          // 0=hi, 1=lo
            const int rem  = idx & 1023;
            const int row  = rem >> 3;           // 0..127
            const int c16  = rem & 7;
            const uint4* src = half ? ql4 : qh4;
            uint4 v = src[gbase + (q0 + row) * 128 + c16];
            uint32_t dst = sb + half * 16384 + (row >> 6) * 8192
                         + sw128((uint32_t)((row & 63) * 128 + c16 * 16));
            asm volatile("st.shared.v4.b32 [%0], {%1,%2,%3,%4};" ::
                "r"(dst), "r"(v.x), "r"(v.y), "r"(v.z), "r"(v.w) : "memory");
        }
    }
    __syncthreads();

    // ---- load Q fragments (held in registers for the whole CTA)
    const int wr = warp * 16;
    uint32_t qh[4][4], ql[4][4];
    {
        const uint32_t qb_h = sb + (wr >> 6) * 8192;
        const uint32_t qb_l = sb + 16384 + (wr >> 6) * 8192;
        const int lrow = (wr & 63) + (lane & 15);
#pragma unroll
        for (int ks = 0; ks < 4; ks++) {
            uint32_t off = sw128((uint32_t)(lrow * 128 + ks * 32 + ((lane >> 4) << 4)));
            ldsm4(qb_h + off, qh[ks][0], qh[ks][1], qh[ks][2], qh[ks][3]);
            ldsm4(qb_l + off, ql[ks][0], ql[ks][1], ql[ks][2], ql[ks][3]);
        }
    }
    __syncthreads();

    float o[8][4];
#pragma unroll
    for (int i = 0; i < 8; i++)
#pragma unroll
        for (int j = 0; j < 4; j++) o[i][j] = 0.f;
    float m0 = -FLT_MAX, m1 = -FLT_MAX, l0 = 0.f, l1 = 0.f;

    const uint4* kh4 = (const uint4*)Kh_g;
    const uint4* kl4 = (const uint4*)Kl_g;
    const uint4* vh4 = (const uint4*)Vh_g;
    const uint4* vl4 = (const uint4*)Vl_g;

    for (int kt = 0; kt < SS / 64; kt++) {
        const int k0 = kt * 64;
        // ---- stage K/V tiles: buf0=Kh, buf1=Kl, buf2=Vh, buf3=Vl
#pragma unroll
        for (int j = 0; j < 2; j++) {
            const int idx = tid + j * 256;       // 0..511
            const int row = idx >> 3;            // 0..63
            const int c16 = idx & 7;
            const int gsrc = gbase + (k0 + row) * 128 + c16;
            const uint32_t sw = sw128((uint32_t)(row * 128 + c16 * 16));
            uint4 a = kh4[gsrc];
            uint4 c = kl4[gsrc];
            uint4 d = vh4[gsrc];
            uint4 e = vl4[gsrc];
            asm volatile("st.shared.v4.b32 [%0], {%1,%2,%3,%4};" ::
                "r"(sb + sw), "r"(a.x), "r"(a.y), "r"(a.z), "r"(a.w) : "memory");
            asm volatile("st.shared.v4.b32 [%0], {%1,%2,%3,%4};" ::
                "r"(sb + 8192 + sw), "r"(c.x), "r"(c.y), "r"(c.z), "r"(c.w) : "memory");
            asm volatile("st.shared.v4.b32 [%0], {%1,%2,%3,%4};" ::
                "r"(sb + 16384 + sw), "r"(d.x), "r"(d.y), "r"(d.z), "r"(d.w) : "memory");
            asm volatile("st.shared.v4.b32 [%0], {%1,%2,%3,%4};" ::
                "r"(sb + 24576 + sw), "r"(e.x), "r"(e.y), "r"(e.z), "r"(e.w) : "memory");
        }
        __syncthreads();

        // ---- S = Q K^T (3-term compensated)
        float s[8][4];
#pragma unroll
        for (int i = 0; i < 8; i++)
#pragma unroll
            for (int j = 0; j < 4; j++) s[i][j] = 0.f;

        const int t8 = lane >> 3;
#pragma unroll
        for (int ks = 0; ks < 4; ks++) {
#pragma unroll
            for (int np = 0; np < 4; np++) {
                const uint32_t off = sw128((uint32_t)(
                    (np * 16 + ((t8 >> 1) << 3) + (lane & 7)) * 128 + (t8 & 1) * 16 + ks * 32));
                uint32_t h0, h1, h2, h3, e0, e1, e2, e3;
                ldsm4(sb + off, h0, h1, h2, h3);
                ldsm4(sb + 8192 + off, e0, e1, e2, e3);
                mma16816(s[2 * np],     qh[ks], h0, h1);
                mma16816(s[2 * np],     qh[ks], e0, e1);
                mma16816(s[2 * np],     ql[ks], h0, h1);
                mma16816(s[2 * np + 1], qh[ks], h2, h3);
                mma16816(s[2 * np + 1], qh[ks], e2, e3);
                mma16816(s[2 * np + 1], ql[ks], h2, h3);
            }
        }

        // ---- online softmax (rows: lane>>2 and +8; 4 lanes/row)
        float mn0 = -FLT_MAX, mn1 = -FLT_MAX;
#pragma unroll
        for (int nf = 0; nf < 8; nf++) {
            s[nf][0] *= 0.125f; s[nf][1] *= 0.125f;
            s[nf][2] *= 0.125f; s[nf][3] *= 0.125f;
            mn0 = fmaxf(mn0, fmaxf(s[nf][0], s[nf][1]));
            mn1 = fmaxf(mn1, fmaxf(s[nf][2], s[nf][3]));
        }
        mn0 = fmaxf(mn0, __shfl_xor_sync(0xffffffffu, mn0, 1));
        mn0 = fmaxf(mn0, __shfl_xor_sync(0xffffffffu, mn0, 2));
        mn1 = fmaxf(mn1, __shfl_xor_sync(0xffffffffu, mn1, 1));
        mn1 = fmaxf(mn1, __shfl_xor_sync(0xffffffffu, mn1, 2));
        mn0 = fmaxf(m0, mn0);
        mn1 = fmaxf(m1, mn1);
        const float f0 = __expf(m0 - mn0);
        const float f1 = __expf(m1 - mn1);
        m0 = mn0; m1 = mn1;

        float rs0 = 0.f, rs1 = 0.f;
        uint32_t pah[4][4], pal[4][4];
#pragma unroll
        for (int nf = 0; nf < 8; nf++) {
            float p0 = __expf(s[nf][0] - m0);
            float p1 = __expf(s[nf][1] - m0);
            float p2 = __expf(s[nf][2] - m1);
            float p3 = __expf(s[nf][3] - m1);
            rs0 += p0 + p1;
            rs1 += p2 + p3;
            __nv_bfloat16 b0 = __float2bfloat16_rn(p0);
            __nv_bfloat16 b1 = __float2bfloat16_rn(p1);
            __nv_bfloat16 b2 = __float2bfloat16_rn(p2);
            __nv_bfloat16 b3 = __float2bfloat16_rn(p3);
            __nv_bfloat16 c0 = __float2bfloat16_rn(p0 - __bfloat162float(b0));
            __nv_bfloat16 c1 = __float2bfloat16_rn(p1 - __bfloat162float(b1));
            __nv_bfloat16 c2 = __float2bfloat16_rn(p2 - __bfloat162float(b2));
            __nv_bfloat16 c3 = __float2bfloat16_rn(p3 - __bfloat162float(b3));
            const int kf = nf >> 1;
            const int rr = (nf & 1) * 2;
            pah[kf][rr]     = packbf(b0, b1);
            pah[kf][rr + 1] = packbf(b2, b3);
            pal[kf][rr]     = packbf(c0, c1);
            pal[kf][rr + 1] = packbf(c2, c3);
        }
        rs0 += __shfl_xor_sync(0xffffffffu, rs0, 1);
        rs0 += __shfl_xor_sync(0xffffffffu, rs0, 2);
        rs1 += __shfl_xor_sync(0xffffffffu, rs1, 1);
        rs1 += __shfl_xor_sync(0xffffffffu, rs1, 2);
        l0 = l0 * f0 + rs0;
        l1 = l1 * f1 + rs1;
#pragma unroll
        for (int nf = 0; nf < 8; nf++) {
            o[nf][0] *= f0; o[nf][1] *= f0;
            o[nf][2] *= f1; o[nf][3] *= f1;
        }

        // ---- O += P V (3-term compensated); V via ldmatrix.trans
#pragma unroll
        for (int kf = 0; kf < 4; kf++) {
#pragma unroll
            for (int np = 0; np < 4; np++) {
                const uint32_t off = sw128((uint32_t)(
                    (kf * 16 + (lane & 8) + (lane & 7)) * 128 + np * 32 + ((lane >> 4) << 4)));
                uint32_t v0, v1, v2, v3, w0, w1, w2, w3;
                ldsm4t(sb + 16384 + off, v0, v1, v2, v3);
                ldsm4t(sb + 24576 + off, w0, w1, w2, w3);
                mma16816(o[2 * np],     pah[kf], v0, v1);
                mma16816(o[2 * np],     pah[kf], w0, w1);
                mma16816(o[2 * np],     pal[kf], v0, v1);
                mma16816(o[2 * np + 1], pah[kf], v2, v3);
                mma16816(o[2 * np + 1], pah[kf], w2, w3);
                mma16816(o[2 * np + 1], pal[kf], v2, v3);
            }
        }
        __syncthreads();
    }

    // ---- epilogue: normalize, hi/lo split, store
    const float inv0 = 1.f / l0;
    const float inv1 = 1.f / l1;
    const int row0 = q0 + wr + (lane >> 2);
    const int colb = h * 64 + (lane & 3) * 2;
#pragma unroll
    for (int nf = 0; nf < 8; nf++) {
        const int col = colb + nf * 8;
        float v0 = o[nf][0] * inv0, v1 = o[nf][1] * inv0;
        float v2 = o[nf][2] * inv1, v3 = o[nf][3] * inv1;
        __nv_bfloat16 h0 = __float2bfloat16_rn(v0);
        __nv_bfloat16 h1 = __float2bfloat16_rn(v1);
        __nv_bfloat16 h2 = __float2bfloat16_rn(v2);
        __nv_bfloat16 h3 = __float2bfloat16_rn(v3);
        __nv_bfloat16 e0 = __float2bfloat16_rn(v0 - __bfloat162float(h0));
        __nv_bfloat16 e1 = __float2bfloat16_rn(v1 - __bfloat162float(h1));
        __nv_bfloat16 e2 = __float2bfloat16_rn(v2 - __bfloat162float(h2));
        __nv_bfloat16 e3 = __float2bfloat16_rn(v3 - __bfloat162float(h3));
        const size_t r0i = (size_t)(b * SS + row0) * EDIM + col;
        const size_t r1i = (size_t)(b * SS + row0 + 8) * EDIM + col;
        *(__nv_bfloat162*)&Ch_g[r0i] = __nv_bfloat162(h0, h1);
        *(__nv_bfloat162*)&Ch_g[r1i] = __nv_bfloat162(h2, h3);
        *(__nv_bfloat162*)&Cl_g[r0i] = __nv_bfloat162(e0, e1);
        *(__nv_bfloat162*)&Cl_g[r1i] = __nv_bfloat162(e2, e3);
    }
}

// ---------------------------------------------------------------------------
// Launch sequence (graph-capturable, no allocs)
// ---------------------------------------------------------------------------
extern "C" void kernel_launch(void* const* d_in, const int* in_sizes, int n_in,
                              void* d_out, int out_size)
{
    const float* x  = (const float*)d_in[0];
    const float* Wq = (const float*)d_in[1];
    const float* bq = (const float*)d_in[2];
    const float* Wk = (const float*)d_in[3];
    const float* bk = (const float*)d_in[4];
    const float* Wv = (const float*)d_in[5];
    const float* bv = (const float*)d_in[6];
    const float* Wo = (const float*)d_in[7];
    const float* bo = (const float*)d_in[8];
    float* out = (float*)d_out;

    __nv_bfloat16 *xh, *xl, *ch, *cl;
    __nv_bfloat16 *qh, *qlp, *kh, *kl, *vh, *vl;
    __nv_bfloat16 *wqh, *wql, *wkh, *wkl, *wvh, *wvl, *woh, *wol;
    cudaGetSymbolAddress((void**)&xh, g_xh);   cudaGetSymbolAddress((void**)&xl, g_xl);
    cudaGetSymbolAddress((void**)&ch, g_ch);   cudaGetSymbolAddress((void**)&cl, g_cl);
    cudaGetSymbolAddress((void**)&qh, g_Qh);   cudaGetSymbolAddress((void**)&qlp, g_Ql);
    cudaGetSymbolAddress((void**)&kh, g_Kh);   cudaGetSymbolAddress((void**)&kl, g_Kl);
    cudaGetSymbolAddress((void**)&vh, g_Vh);   cudaGetSymbolAddress((void**)&vl, g_Vl);
    cudaGetSymbolAddress((void**)&wqh, g_Wqh); cudaGetSymbolAddress((void**)&wql, g_Wql);
    cudaGetSymbolAddress((void**)&wkh, g_Wkh); cudaGetSymbolAddress((void**)&wkl, g_Wkl);
    cudaGetSymbolAddress((void**)&wvh, g_Wvh); cudaGetSymbolAddress((void**)&wvl, g_Wvl);
    cudaGetSymbolAddress((void**)&woh, g_Woh); cudaGetSymbolAddress((void**)&wol, g_Wol);

    static int attr_set = 0;
    if (!attr_set) {
        cudaFuncSetAttribute(hmma_gemm_bias<true>,
                             cudaFuncAttributeMaxDynamicSharedMemorySize, GEMM_SMEM);
        cudaFuncSetAttribute(hmma_gemm_bias<false>,
                             cudaFuncAttributeMaxDynamicSharedMemorySize, GEMM_SMEM);
        cudaFuncSetAttribute(attn_hmma,
                             cudaFuncAttributeMaxDynamicSharedMemorySize, ATT_SMEM);
        attr_set = 1;
    }

    // 1) split x; transpose+split weights
    const int n4 = MTOT * EDIM / 4;
    xsplit<<<(n4 + 255) / 256, 256>>>((const float4*)x,
        (__nv_bfloat162*)xh, (__nv_bfloat162*)xl, n4);
    dim3 wt(32, 8), wg(EDIM / 32, EDIM / 32);
    wsplit_t<<<wg, wt>>>(Wq, wqh, wql);
    wsplit_t<<<wg, wt>>>(Wk, wkh, wkl);
    wsplit_t<<<wg, wt>>>(Wv, wvh, wvl);
    wsplit_t<<<wg, wt>>>(Wo, woh, wol);

    // 2) QKV projections, bf16 hi/lo outputs
    dim3 gg(EDIM / 128, MTOT / 128);
    hmma_gemm_bias<true><<<gg, 256, GEMM_SMEM>>>(xh, xl, wqh, wql, bq, nullptr, qh, qlp);
    hmma_gemm_bias<true><<<gg, 256, GEMM_SMEM>>>(xh, xl, wkh, wkl, bk, nullptr, kh, kl);
    hmma_gemm_bias<true><<<gg, 256, GEMM_SMEM>>>(xh, xl, wvh, wvl, bv, nullptr, vh, vl);

    // 3) attention on tensor cores
    attn_hmma<<<dim3(SS / 128, BB * HEADS), 256, ATT_SMEM>>>(
        qh, qlp, kh, kl, vh, vl, ch, cl);

    // 4) output projection, fp32 output
    hmma_gemm_bias<false><<<gg, 256, GEMM_SMEM>>>(ch, cl, woh, wol, bo, out, nullptr, nullptr);
}

// round 16
// speedup vs baseline: 3.1901x; 1.2015x over previous
#include <cuda_runtime.h>
#include <cuda_bf16.h>
#include <math.h>
#include <float.h>
#include <stdint.h>

#define EDIM   1024
#define HEADS  16
#define DH     64
#define BB     2
#define SS     2048
#define MTOT   (BB * SS)      // 4096

// ---------------- scratch (__device__ globals; no allocs allowed) ----------
__device__ __nv_bfloat16 g_xh[MTOT * EDIM], g_xl[MTOT * EDIM];
__device__ __nv_bfloat16 g_Qh[MTOT * EDIM], g_Ql[MTOT * EDIM];
__device__ __nv_bfloat16 g_Kh[MTOT * EDIM], g_Kl[MTOT * EDIM];
__device__ __nv_bfloat16 g_Vh[MTOT * EDIM], g_Vl[MTOT * EDIM];
__device__ __nv_bfloat16 g_ch[MTOT * EDIM], g_cl[MTOT * EDIM];
__device__ __nv_bfloat16 g_Wqh[EDIM * EDIM], g_Wql[EDIM * EDIM];
__device__ __nv_bfloat16 g_Wkh[EDIM * EDIM], g_Wkl[EDIM * EDIM];
__device__ __nv_bfloat16 g_Wvh[EDIM * EDIM], g_Wvl[EDIM * EDIM];
__device__ __nv_bfloat16 g_Woh[EDIM * EDIM], g_Wol[EDIM * EDIM];

// ---------------- helpers ---------------------------------------------------
__device__ __forceinline__ uint32_t smem_u32(const void* p) {
    return (uint32_t)__cvta_generic_to_shared(p);
}

__device__ __forceinline__ void ldsm4(uint32_t addr, uint32_t& r0, uint32_t& r1,
                                      uint32_t& r2, uint32_t& r3) {
    asm volatile("ldmatrix.sync.aligned.m8n8.x4.shared.b16 {%0,%1,%2,%3}, [%4];"
                 : "=r"(r0), "=r"(r1), "=r"(r2), "=r"(r3) : "r"(addr));
}

__device__ __forceinline__ void ldsm4t(uint32_t addr, uint32_t& r0, uint32_t& r1,
                                       uint32_t& r2, uint32_t& r3) {
    asm volatile("ldmatrix.sync.aligned.m8n8.x4.trans.shared.b16 {%0,%1,%2,%3}, [%4];"
                 : "=r"(r0), "=r"(r1), "=r"(r2), "=r"(r3) : "r"(addr));
}

__device__ __forceinline__ void mma16816(float* c, const uint32_t* a,
                                         uint32_t b0, uint32_t b1) {
    asm volatile(
        "mma.sync.aligned.m16n8k16.row.col.f32.bf16.bf16.f32 "
        "{%0,%1,%2,%3}, {%4,%5,%6,%7}, {%8,%9}, {%0,%1,%2,%3};"
        : "+f"(c[0]), "+f"(c[1]), "+f"(c[2]), "+f"(c[3])
        : "r"(a[0]), "r"(a[1]), "r"(a[2]), "r"(a[3]), "r"(b0), "r"(b1));
}

__device__ __forceinline__ uint32_t sw128(uint32_t off) {
    return off ^ ((off >> 3) & 0x70);
}

__device__ __forceinline__ uint32_t packbf(__nv_bfloat16 a, __nv_bfloat16 b) {
    __nv_bfloat162 t(a, b);
    return *(uint32_t*)&t;
}

#define CPA16(dst, src) \
    asm volatile("cp.async.cg.shared.global [%0], [%1], 16;" :: "r"(dst), "l"(src) : "memory")
#define CPC() asm volatile("cp.async.commit_group;" ::: "memory")
#define CPW1() asm volatile("cp.async.wait_group 1;" ::: "memory")
#define CPW0() asm volatile("cp.async.wait_group 0;" ::: "memory")

// ---------------------------------------------------------------------------
// Split fp32 -> bf16 hi/lo (elementwise)
// ---------------------------------------------------------------------------
__global__ void xsplit(const float4* __restrict__ in,
                       __nv_bfloat162* __restrict__ h, __nv_bfloat162* __restrict__ l, int n4)
{
    int i = blockIdx.x * blockDim.x + threadIdx.x;
    if (i >= n4) return;
    float4 v = in[i];
    __nv_bfloat16 hx = __float2bfloat16_rn(v.x);
    __nv_bfloat16 hy = __float2bfloat16_rn(v.y);
    __nv_bfloat16 hz = __float2bfloat16_rn(v.z);
    __nv_bfloat16 hw = __float2bfloat16_rn(v.w);
    __nv_bfloat16 lx = __float2bfloat16_rn(v.x - __bfloat162float(hx));
    __nv_bfloat16 ly = __float2bfloat16_rn(v.y - __bfloat162float(hy));
    __nv_bfloat16 lz = __float2bfloat16_rn(v.z - __bfloat162float(hz));
    __nv_bfloat16 lw = __float2bfloat16_rn(v.w - __bfloat162float(hw));
    h[2 * i]     = __nv_bfloat162(hx, hy);
    h[2 * i + 1] = __nv_bfloat162(hz, hw);
    l[2 * i]     = __nv_bfloat162(lx, ly);
    l[2 * i + 1] = __nv_bfloat162(lz, lw);
}

// ---------------------------------------------------------------------------
// Fused transpose + split for all 4 weights: W[k][n] -> Th/Tl[n][k] bf16
// ---------------------------------------------------------------------------
struct WPack {
    const float* W[4];
    __nv_bfloat16* Th[4];
    __nv_bfloat16* Tl[4];
};

__global__ void wsplit_all(WPack p)
{
    __shared__ float t[32][33];
    const float* W = p.W[blockIdx.z];
    __nv_bfloat16* Th = p.Th[blockIdx.z];
    __nv_bfloat16* Tl = p.Tl[blockIdx.z];
    const int n0 = blockIdx.x * 32, k0 = blockIdx.y * 32;
    const int x = threadIdx.x, y = threadIdx.y;   // 32 x 8
#pragma unroll
    for (int i = y; i < 32; i += 8)
        t[i][x] = W[(size_t)(k0 + i) * EDIM + n0 + x];
    __syncthreads();
#pragma unroll
    for (int i = y; i < 32; i += 8) {
        float v = t[x][i];
        __nv_bfloat16 hv = __float2bfloat16_rn(v);
        __nv_bfloat16 lv = __float2bfloat16_rn(v - __bfloat162float(hv));
        size_t o = (size_t)(n0 + i) * EDIM + k0 + x;
        Th[o] = hv;
        Tl[o] = lv;
    }
}

// ---------------------------------------------------------------------------
// HMMA bf16x3 GEMM + bias, cp.async double-buffered.
// blockIdx.z selects the weight/bias/output set (fused QKV).
// SPLIT=true: write bf16 hi/lo; else fp32 to Cout.
// ---------------------------------------------------------------------------
struct QKVPack {
    const __nv_bfloat16* Bh[3];
    const __nv_bfloat16* Bl[3];
    const float* bias[3];
    __nv_bfloat16* Oh[3];
    __nv_bfloat16* Ol[3];
};

#define GEMM_SMEM (2 * 65536 + 1024)

template <bool SPLIT>
__global__ __launch_bounds__(256) void hmma_gemm_bias(
    const __nv_bfloat16* __restrict__ Ah, const __nv_bfloat16* __restrict__ Al,
    QKVPack p, float* __restrict__ Cout)
{
    extern __shared__ char smem[];
    const uint32_t sbase = (smem_u32(smem) + 1023) & ~1023u;

    const int z = blockIdx.z;
    const uint4* gAh = (const uint4*)Ah;
    const uint4* gAl = (const uint4*)Al;
    const uint4* gBh = (const uint4*)p.Bh[z];
    const uint4* gBl = (const uint4*)p.Bl[z];
    const float* bias = p.bias[z];

    const int tid  = threadIdx.x;
    const int wid  = tid >> 5;
    const int lane = tid & 31;
    const int wm   = wid >> 2;
    const int wn   = wid & 3;
    const int m0   = blockIdx.y * 128;
    const int n0   = blockIdx.x * 128;

    const int a_row = lane & 15;
    const int a_kb  = (lane >> 4) * 16;
    const int b_row = (lane & 7) | ((lane & 16) >> 1);
    const int b_kb  = (lane & 8) * 2;

    float acc[4][4][4];
#pragma unroll
    for (int i = 0; i < 4; i++)
#pragma unroll
        for (int j = 0; j < 4; j++)
#pragma unroll
            for (int r = 0; r < 4; r++) acc[i][j][r] = 0.f;

    // cp.async staging of one 128x64 K-chunk (4 tiles of 16KB) into buffer bu
    auto stage = [&](int kc, int bu) {
        const uint32_t bb = sbase + bu * 65536;
#pragma unroll
        for (int t = 0; t < 4; t++) {
            const int idx = tid + t * 256;
            const int row = idx >> 3;
            const int c16 = idx & 7;
            const uint32_t sw = sw128((uint32_t)(row * 128 + c16 * 16));
            const int ga = (m0 + row) * 128 + kc * 8 + c16;
            const int gb = (n0 + row) * 128 + kc * 8 + c16;
            CPA16(bb + sw,         gAh + ga);
            CPA16(bb + 16384 + sw, gAl + ga);
            CPA16(bb + 32768 + sw, gBh + gb);
            CPA16(bb + 49152 + sw, gBl + gb);
        }
        CPC();
    };

    stage(0, 0);

    for (int kc = 0; kc < 16; kc++) {
        if (kc < 15) { stage(kc + 1, (kc + 1) & 1); CPW1(); }
        else         { CPW0(); }
        __syncthreads();

        const uint32_t bb  = sbase + (kc & 1) * 65536;
        const uint32_t sAh = bb;
        const uint32_t sAl = bb + 16384;
        const uint32_t sBh = bb + 32768;
        const uint32_t sBl = bb + 49152;

#pragma unroll
        for (int s = 0; s < 4; s++) {
            const int kb = s * 32;
            uint32_t ah[16], al[16], bh[8], bl[8];
#pragma unroll
            for (int mf = 0; mf < 4; mf++) {
                const uint32_t off = (uint32_t)((wm * 64 + mf * 16 + a_row) * 128 + a_kb + kb);
                const uint32_t sw = sw128(off);
                ldsm4(sAh + sw, ah[mf * 4], ah[mf * 4 + 1], ah[mf * 4 + 2], ah[mf * 4 + 3]);
                ldsm4(sAl + sw, al[mf * 4], al[mf * 4 + 1], al[mf * 4 + 2], al[mf * 4 + 3]);
            }
#pragma unroll
            for (int nb = 0; nb < 2; nb++) {
                const uint32_t off = (uint32_t)((wn * 32 + nb * 16 + b_row) * 128 + b_kb + kb);
                const uint32_t sw = sw128(off);
                ldsm4(sBh + sw, bh[nb * 4], bh[nb * 4 + 1], bh[nb * 4 + 2], bh[nb * 4 + 3]);
                ldsm4(sBl + sw, bl[nb * 4], bl[nb * 4 + 1], bl[nb * 4 + 2], bl[nb * 4 + 3]);
            }
#pragma unroll
            for (int mf = 0; mf < 4; mf++)
#pragma unroll
                for (int nf = 0; nf < 4; nf++) {
                    mma16816(acc[mf][nf], &ah[mf * 4], bh[nf * 2], bh[nf * 2 + 1]);
                    mma16816(acc[mf][nf], &ah[mf * 4], bl[nf * 2], bl[nf * 2 + 1]);
                    mma16816(acc[mf][nf], &al[mf * 4], bh[nf * 2], bh[nf * 2 + 1]);
                }
        }
        __syncthreads();
    }

    const int er = lane >> 2;
    const int ec = (lane & 3) * 2;
#pragma unroll
    for (int mf = 0; mf < 4; mf++) {
#pragma unroll
        for (int nf = 0; nf < 4; nf++) {
            const int col  = n0 + wn * 32 + nf * 8 + ec;
            const float b0 = bias[col], b1 = bias[col + 1];
            const int row0 = m0 + wm * 64 + mf * 16 + er;
            float v0 = acc[mf][nf][0] + b0, v1 = acc[mf][nf][1] + b1;
            float v2 = acc[mf][nf][2] + b0, v3 = acc[mf][nf][3] + b1;
            if (SPLIT) {
                __nv_bfloat16* Oh = p.Oh[z];
                __nv_bfloat16* Ol = p.Ol[z];
                __nv_bfloat16 h0 = __float2bfloat16_rn(v0);
                __nv_bfloat16 h1 = __float2bfloat16_rn(v1);
                __nv_bfloat16 h2 = __float2bfloat16_rn(v2);
                __nv_bfloat16 h3 = __float2bfloat16_rn(v3);
                __nv_bfloat16 l0 = __float2bfloat16_rn(v0 - __bfloat162float(h0));
                __nv_bfloat16 l1 = __float2bfloat16_rn(v1 - __bfloat162float(h1));
                __nv_bfloat16 l2 = __float2bfloat16_rn(v2 - __bfloat162float(h2));
                __nv_bfloat16 l3 = __float2bfloat16_rn(v3 - __bfloat162float(h3));
                *(__nv_bfloat162*)&Oh[(size_t)row0 * EDIM + col]       = __nv_bfloat162(h0, h1);
                *(__nv_bfloat162*)&Oh[(size_t)(row0 + 8) * EDIM + col] = __nv_bfloat162(h2, h3);
                *(__nv_bfloat162*)&Ol[(size_t)row0 * EDIM + col]       = __nv_bfloat162(l0, l1);
                *(__nv_bfloat162*)&Ol[(size_t)(row0 + 8) * EDIM + col] = __nv_bfloat162(l2, l3);
            } else {
                *(float2*)&Cout[(size_t)row0 * EDIM + col]       = make_float2(v0, v1);
                *(float2*)&Cout[(size_t)(row0 + 8) * EDIM + col] = make_float2(v2, v3);
            }
        }
    }
}

// ---------------------------------------------------------------------------
// HMMA flash attention, bf16 hi/lo compensated, cp.async double-buffered K/V.
// CTA: 128 queries x one (b,h). 8 warps x 16 query rows. Key tile = 64.
// smem: Q region 32KB (persistent) + 2 x 32KB K/V buffers.
// ---------------------------------------------------------------------------
#define ATT_SMEM (32768 + 2 * 32768 + 1024)

__global__ __launch_bounds__(256) void attn_hmma(
    const __nv_bfloat16* __restrict__ Qh_g, const __nv_bfloat16* __restrict__ Ql_g,
    const __nv_bfloat16* __restrict__ Kh_g, const __nv_bfloat16* __restrict__ Kl_g,
    const __nv_bfloat16* __restrict__ Vh_g, const __nv_bfloat16* __restrict__ Vl_g,
    __nv_bfloat16* __restrict__ Ch_g, __nv_bfloat16* __restrict__ Cl_g)
{
    extern __shared__ char smem[];
    const uint32_t sQ  = (smem_u32(smem) + 1023) & ~1023u;
    const uint32_t sKV = sQ + 32768;

    const int tid  = threadIdx.x;
    const int lane = tid & 31;
    const int warp = tid >> 5;
    const int q0   = blockIdx.x * 128;
    const int bh   = blockIdx.y;
    const int b    = bh >> 4;
    const int h    = bh & 15;
    const int gbase = (b * SS) * 128 + h * 8;     // uint4 index of (row, h*64)

    const uint4* qh4 = (const uint4*)Qh_g;
    const uint4* ql4 = (const uint4*)Ql_g;
    const uint4* kh4 = (const uint4*)Kh_g;
    const uint4* kl4 = (const uint4*)Kl_g;
    const uint4* vh4 = (const uint4*)Vh_g;
    const uint4* vl4 = (const uint4*)Vl_g;

    // ---- stage Q (cp.async): hi rows -> sQ[0:16K), lo -> sQ[16K:32K)
#pragma unroll
    for (int t = 0; t < 8; t++) {
        const int idx  = tid + t * 256;      // 0..2047
        const int half = idx >> 10;
        const int rem  = idx & 1023;
        const int row  = rem >> 3;
        const int c16  = rem & 7;
        const uint4* src = half ? ql4 : qh4;
        const uint32_t dst = sQ + half * 16384 + (row >> 6) * 8192
                           + sw128((uint32_t)((row & 63) * 128 + c16 * 16));
        CPA16(dst, src + gbase + (q0 + row) * 128 + c16);
    }
    CPC();

    // K/V tile staging: buf layout Kh|Kl|Vh|Vl (8KB each)
    auto stageKV = [&](int kt, int bu) {
        const int k0 = kt * 64;
        const uint32_t bb = sKV + bu * 32768;
#pragma unroll
        for (int j = 0; j < 2; j++) {
            const int idx = tid + j * 256;       // 0..511
            const int row = idx >> 3;
            const int c16 = idx & 7;
            const int gsrc = gbase + (k0 + row) * 128 + c16;
            const uint32_t sw = sw128((uint32_t)(row * 128 + c16 * 16));
            CPA16(bb + sw,         kh4 + gsrc);
            CPA16(bb + 8192 + sw,  kl4 + gsrc);
            CPA16(bb + 16384 + sw, vh4 + gsrc);
            CPA16(bb + 24576 + sw, vl4 + gsrc);
        }
        CPC();
    };

    stageKV(0, 0);
    CPW0();
    __syncthreads();

    // ---- load Q fragments (registers, whole kernel)
    const int wr = warp * 16;
    uint32_t qh[4][4], ql[4][4];
    {
        const uint32_t qb_h = sQ + (wr >> 6) * 8192;
        const uint32_t qb_l = sQ + 16384 + (wr >> 6) * 8192;
        const int lrow = (wr & 63) + (lane & 15);
#pragma unroll
        for (int ks = 0; ks < 4; ks++) {
            uint32_t off = sw128((uint32_t)(lrow * 128 + ks * 32 + ((lane >> 4) << 4)));
            ldsm4(qb_h + off, qh[ks][0], qh[ks][1], qh[ks][2], qh[ks][3]);
            ldsm4(qb_l + off, ql[ks][0], ql[ks][1], ql[ks][2], ql[ks][3]);
        }
    }

    float o[8][4];
#pragma unroll
    for (int i = 0; i < 8; i++)
#pragma unroll
        for (int j = 0; j < 4; j++) o[i][j] = 0.f;
    float m0 = -FLT_MAX, m1 = -FLT_MAX, l0 = 0.f, l1 = 0.f;

    const int NT = SS / 64;
    for (int kt = 0; kt < NT; kt++) {
        if (kt < NT - 1) { stageKV(kt + 1, (kt + 1) & 1); CPW1(); }
        else             { CPW0(); }
        __syncthreads();

        const uint32_t bb = sKV + (kt & 1) * 32768;

        // ---- S = Q K^T (3-term compensated)
        float s[8][4];
#pragma unroll
        for (int i = 0; i < 8; i++)
#pragma unroll
            for (int j = 0; j < 4; j++) s[i][j] = 0.f;

        const int t8 = lane >> 3;
#pragma unroll
        for (int ks = 0; ks < 4; ks++) {
#pragma unroll
            for (int np = 0; np < 4; np++) {
                const uint32_t off = sw128((uint32_t)(
                    (np * 16 + ((t8 >> 1) << 3) + (lane & 7)) * 128 + (t8 & 1) * 16 + ks * 32));
                uint32_t h0, h1, h2, h3, e0, e1, e2, e3;
                ldsm4(bb + off, h0, h1, h2, h3);
                ldsm4(bb + 8192 + off, e0, e1, e2, e3);
                mma16816(s[2 * np],     qh[ks], h0, h1);
                mma16816(s[2 * np],     qh[ks], e0, e1);
                mma16816(s[2 * np],     ql[ks], h0, h1);
                mma16816(s[2 * np + 1], qh[ks], h2, h3);
                mma16816(s[2 * np + 1], qh[ks], e2, e3);
                mma16816(s[2 * np + 1], ql[ks], h2, h3);
            }
        }

        // ---- online softmax
        float mn0 = -FLT_MAX, mn1 = -FLT_MAX;
#pragma unroll
        for (int nf = 0; nf < 8; nf++) {
            s[nf][0] *= 0.125f; s[nf][1] *= 0.125f;
            s[nf][2] *= 0.125f; s[nf][3] *= 0.125f;
            mn0 = fmaxf(mn0, fmaxf(s[nf][0], s[nf][1]));
            mn1 = fmaxf(mn1, fmaxf(s[nf][2], s[nf][3]));
        }
        mn0 = fmaxf(mn0, __shfl_xor_sync(0xffffffffu, mn0, 1));
        mn0 = fmaxf(mn0, __shfl_xor_sync(0xffffffffu, mn0, 2));
        mn1 = fmaxf(mn1, __shfl_xor_sync(0xffffffffu, mn1, 1));
        mn1 = fmaxf(mn1, __shfl_xor_sync(0xffffffffu, mn1, 2));
        mn0 = fmaxf(m0, mn0);
        mn1 = fmaxf(m1, mn1);
        const float f0 = __expf(m0 - mn0);
        const float f1 = __expf(m1 - mn1);
        m0 = mn0; m1 = mn1;

        float rs0 = 0.f, rs1 = 0.f;
        uint32_t pah[4][4], pal[4][4];
#pragma unroll
        for (int nf = 0; nf < 8; nf++) {
            float p0 = __expf(s[nf][0] - m0);
            float p1 = __expf(s[nf][1] - m0);
            float p2 = __expf(s[nf][2] - m1);
            float p3 = __expf(s[nf][3] - m1);
            rs0 += p0 + p1;
            rs1 += p2 + p3;
            __nv_bfloat16 b0 = __float2bfloat16_rn(p0);
            __nv_bfloat16 b1 = __float2bfloat16_rn(p1);
            __nv_bfloat16 b2 = __float2bfloat16_rn(p2);
            __nv_bfloat16 b3 = __float2bfloat16_rn(p3);
            __nv_bfloat16 c0 = __float2bfloat16_rn(p0 - __bfloat162float(b0));
            __nv_bfloat16 c1 = __float2bfloat16_rn(p1 - __bfloat162float(b1));
            __nv_bfloat16 c2 = __float2bfloat16_rn(p2 - __bfloat162float(b2));
            __nv_bfloat16 c3 = __float2bfloat16_rn(p3 - __bfloat162float(b3));
            const int kf = nf >> 1;
            const int rr = (nf & 1) * 2;
            pah[kf][rr]     = packbf(b0, b1);
            pah[kf][rr + 1] = packbf(b2, b3);
            pal[kf][rr]     = packbf(c0, c1);
            pal[kf][rr + 1] = packbf(c2, c3);
        }
        rs0 += __shfl_xor_sync(0xffffffffu, rs0, 1);
        rs0 += __shfl_xor_sync(0xffffffffu, rs0, 2);
        rs1 += __shfl_xor_sync(0xffffffffu, rs1, 1);
        rs1 += __shfl_xor_sync(0xffffffffu, rs1, 2);
        l0 = l0 * f0 + rs0;
        l1 = l1 * f1 + rs1;
#pragma unroll
        for (int nf = 0; nf < 8; nf++) {
            o[nf][0] *= f0; o[nf][1] *= f0;
            o[nf][2] *= f1; o[nf][3] *= f1;
        }

        // ---- O += P V (3-term compensated)
#pragma unroll
        for (int kf = 0; kf < 4; kf++) {
#pragma unroll
            for (int np = 0; np < 4; np++) {
                const uint32_t off = sw128((uint32_t)(
                    (kf * 16 + (lane & 8) + (lane & 7)) * 128 + np * 32 + ((lane >> 4) << 4)));
                uint32_t v0, v1, v2, v3, w0, w1, w2, w3;
                ldsm4t(bb + 16384 + off, v0, v1, v2, v3);
                ldsm4t(bb + 24576 + off, w0, w1, w2, w3);
                mma16816(o[2 * np],     pah[kf], v0, v1);
                mma16816(o[2 * np],     pah[kf], w0, w1);
                mma16816(o[2 * np],     pal[kf], v0, v1);
                mma16816(o[2 * np + 1], pah[kf], v2, v3);
                mma16816(o[2 * np + 1], pah[kf], w2, w3);
                mma16816(o[2 * np + 1], pal[kf], v2, v3);
            }
        }
        __syncthreads();
    }

    // ---- epilogue: normalize, hi/lo split, store
    const float inv0 = 1.f / l0;
    const float inv1 = 1.f / l1;
    const int row0 = q0 + wr + (lane >> 2);
    const int colb = h * 64 + (lane & 3) * 2;
#pragma unroll
    for (int nf = 0; nf < 8; nf++) {
        const int col = colb + nf * 8;
        float v0 = o[nf][0] * inv0, v1 = o[nf][1] * inv0;
        float v2 = o[nf][2] * inv1, v3 = o[nf][3] * inv1;
        __nv_bfloat16 h0 = __float2bfloat16_rn(v0);
        __nv_bfloat16 h1 = __float2bfloat16_rn(v1);
        __nv_bfloat16 h2 = __float2bfloat16_rn(v2);
        __nv_bfloat16 h3 = __float2bfloat16_rn(v3);
        __nv_bfloat16 e0 = __float2bfloat16_rn(v0 - __bfloat162float(h0));
        __nv_bfloat16 e1 = __float2bfloat16_rn(v1 - __bfloat162float(h1));
        __nv_bfloat16 e2 = __float2bfloat16_rn(v2 - __bfloat162float(h2));
        __nv_bfloat16 e3 = __float2bfloat16_rn(v3 - __bfloat162float(h3));
        const size_t r0i = (size_t)(b * SS + row0) * EDIM + col;
        const size_t r1i = (size_t)(b * SS + row0 + 8) * EDIM + col;
        *(__nv_bfloat162*)&Ch_g[r0i] = __nv_bfloat162(h0, h1);
        *(__nv_bfloat162*)&Ch_g[r1i] = __nv_bfloat162(h2, h3);
        *(__nv_bfloat162*)&Cl_g[r0i] = __nv_bfloat162(e0, e1);
        *(__nv_bfloat162*)&Cl_g[r1i] = __nv_bfloat162(e2, e3);
    }
}

// ---------------------------------------------------------------------------
// Launch sequence (graph-capturable, no allocs)
// ---------------------------------------------------------------------------
extern "C" void kernel_launch(void* const* d_in, const int* in_sizes, int n_in,
                              void* d_out, int out_size)
{
    const float* x  = (const float*)d_in[0];
    const float* Wq = (const float*)d_in[1];
    const float* bq = (const float*)d_in[2];
    const float* Wk = (const float*)d_in[3];
    const float* bk = (const float*)d_in[4];
    const float* Wv = (const float*)d_in[5];
    const float* bv = (const float*)d_in[6];
    const float* Wo = (const float*)d_in[7];
    const float* bo = (const float*)d_in[8];
    float* out = (float*)d_out;

    __nv_bfloat16 *xh, *xl, *ch, *cl;
    __nv_bfloat16 *qh, *qlp, *kh, *kl, *vh, *vl;
    __nv_bfloat16 *wqh, *wql, *wkh, *wkl, *wvh, *wvl, *woh, *wol;
    cudaGetSymbolAddress((void**)&xh, g_xh);   cudaGetSymbolAddress((void**)&xl, g_xl);
    cudaGetSymbolAddress((void**)&ch, g_ch);   cudaGetSymbolAddress((void**)&cl, g_cl);
    cudaGetSymbolAddress((void**)&qh, g_Qh);   cudaGetSymbolAddress((void**)&qlp, g_Ql);
    cudaGetSymbolAddress((void**)&kh, g_Kh);   cudaGetSymbolAddress((void**)&kl, g_Kl);
    cudaGetSymbolAddress((void**)&vh, g_Vh);   cudaGetSymbolAddress((void**)&vl, g_Vl);
    cudaGetSymbolAddress((void**)&wqh, g_Wqh); cudaGetSymbolAddress((void**)&wql, g_Wql);
    cudaGetSymbolAddress((void**)&wkh, g_Wkh); cudaGetSymbolAddress((void**)&wkl, g_Wkl);
    cudaGetSymbolAddress((void**)&wvh, g_Wvh); cudaGetSymbolAddress((void**)&wvl, g_Wvl);
    cudaGetSymbolAddress((void**)&woh, g_Woh); cudaGetSymbolAddress((void**)&wol, g_Wol);

    static int attr_set = 0;
    if (!attr_set) {
        cudaFuncSetAttribute(hmma_gemm_bias<true>,
                             cudaFuncAttributeMaxDynamicSharedMemorySize, GEMM_SMEM);
        cudaFuncSetAttribute(hmma_gemm_bias<false>,
                             cudaFuncAttributeMaxDynamicSharedMemorySize, GEMM_SMEM);
        cudaFuncSetAttribute(attn_hmma,
                             cudaFuncAttributeMaxDynamicSharedMemorySize, ATT_SMEM);
        attr_set = 1;
    }

    // 1) split x; transpose+split all weights (one launch)
    const int n4 = MTOT * EDIM / 4;
    xsplit<<<(n4 + 255) / 256, 256>>>((const float4*)x,
        (__nv_bfloat162*)xh, (__nv_bfloat162*)xl, n4);
    WPack wp;
    wp.W[0] = Wq; wp.Th[0] = wqh; wp.Tl[0] = wql;
    wp.W[1] = Wk; wp.Th[1] = wkh; wp.Tl[1] = wkl;
    wp.W[2] = Wv; wp.Th[2] = wvh; wp.Tl[2] = wvl;
    wp.W[3] = Wo; wp.Th[3] = woh; wp.Tl[3] = wol;
    wsplit_all<<<dim3(EDIM / 32, EDIM / 32, 4), dim3(32, 8)>>>(wp);

    // 2) fused Q/K/V projections (one launch, z selects set)
    QKVPack pq;
    pq.Bh[0] = wqh; pq.Bl[0] = wql; pq.bias[0] = bq; pq.Oh[0] = qh; pq.Ol[0] = qlp;
    pq.Bh[1] = wkh; pq.Bl[1] = wkl; pq.bias[1] = bk; pq.Oh[1] = kh; pq.Ol[1] = kl;
    pq.Bh[2] = wvh; pq.Bl[2] = wvl; pq.bias[2] = bv; pq.Oh[2] = vh; pq.Ol[2] = vl;
    hmma_gemm_bias<true><<<dim3(EDIM / 128, MTOT / 128, 3), 256, GEMM_SMEM>>>(
        xh, xl, pq, nullptr);

    // 3) attention on tensor cores
    attn_hmma<<<dim3(SS / 128, BB * HEADS), 256, ATT_SMEM>>>(
        qh, qlp, kh, kl, vh, vl, ch, cl);

    // 4) output projection, fp32 output
    QKVPack po;
    po.Bh[0] = woh; po.Bl[0] = wol; po.bias[0] = bo; po.Oh[0] = nullptr; po.Ol[0] = nullptr;
    po.Bh[1] = po.Bh[2] = nullptr; po.Bl[1] = po.Bl[2] = nullptr;
    po.bias[1] = po.bias[2] = nullptr; po.Oh[1] = po.Oh[2] = nullptr; po.Ol[1] = po.Ol[2] = nullptr;
    hmma_gemm_bias<false><<<dim3(EDIM / 128, MTOT / 128, 1), 256, GEMM_SMEM>>>(
        ch, cl, po, out);
}

// round 17
// speedup vs baseline: 3.4389x; 1.0780x over previous
#include <cuda_runtime.h>
#include <cuda_bf16.h>
#include <math.h>
#include <float.h>
#include <stdint.h>

#define EDIM   1024
#define HEADS  16
#define DH     64
#define BB     2
#define SS     2048
#define MTOT   (BB * SS)      // 4096

// ---------------- scratch (__device__ globals; no allocs allowed) ----------
__device__ __nv_bfloat16 g_xh[MTOT * EDIM], g_xl[MTOT * EDIM];
__device__ __nv_bfloat16 g_Qh[MTOT * EDIM], g_Ql[MTOT * EDIM];
__device__ __nv_bfloat16 g_Kh[MTOT * EDIM], g_Kl[MTOT * EDIM];
__device__ __nv_bfloat16 g_Vh[MTOT * EDIM], g_Vl[MTOT * EDIM];
__device__ __nv_bfloat16 g_ch[MTOT * EDIM], g_cl[MTOT * EDIM];
__device__ __nv_bfloat16 g_Wqh[EDIM * EDIM], g_Wql[EDIM * EDIM];
__device__ __nv_bfloat16 g_Wkh[EDIM * EDIM], g_Wkl[EDIM * EDIM];
__device__ __nv_bfloat16 g_Wvh[EDIM * EDIM], g_Wvl[EDIM * EDIM];
__device__ __nv_bfloat16 g_Woh[EDIM * EDIM], g_Wol[EDIM * EDIM];

// ---------------- helpers ---------------------------------------------------
__device__ __forceinline__ uint32_t smem_u32(const void* p) {
    return (uint32_t)__cvta_generic_to_shared(p);
}

__device__ __forceinline__ void ldsm4(uint32_t addr, uint32_t& r0, uint32_t& r1,
                                      uint32_t& r2, uint32_t& r3) {
    asm volatile("ldmatrix.sync.aligned.m8n8.x4.shared.b16 {%0,%1,%2,%3}, [%4];"
                 : "=r"(r0), "=r"(r1), "=r"(r2), "=r"(r3) : "r"(addr));
}

__device__ __forceinline__ void ldsm4t(uint32_t addr, uint32_t& r0, uint32_t& r1,
                                       uint32_t& r2, uint32_t& r3) {
    asm volatile("ldmatrix.sync.aligned.m8n8.x4.trans.shared.b16 {%0,%1,%2,%3}, [%4];"
                 : "=r"(r0), "=r"(r1), "=r"(r2), "=r"(r3) : "r"(addr));
}

__device__ __forceinline__ void mma16816(float* c, const uint32_t* a,
                                         uint32_t b0, uint32_t b1) {
    asm volatile(
        "mma.sync.aligned.m16n8k16.row.col.f32.bf16.bf16.f32 "
        "{%0,%1,%2,%3}, {%4,%5,%6,%7}, {%8,%9}, {%0,%1,%2,%3};"
        : "+f"(c[0]), "+f"(c[1]), "+f"(c[2]), "+f"(c[3])
        : "r"(a[0]), "r"(a[1]), "r"(a[2]), "r"(a[3]), "r"(b0), "r"(b1));
}

__device__ __forceinline__ uint32_t sw128(uint32_t off) {
    return off ^ ((off >> 3) & 0x70);
}

__device__ __forceinline__ uint32_t packbf(__nv_bfloat16 a, __nv_bfloat16 b) {
    __nv_bfloat162 t(a, b);
    return *(uint32_t*)&t;
}

#define CPA16(dst, src) \
    asm volatile("cp.async.cg.shared.global [%0], [%1], 16;" :: "r"(dst), "l"(src) : "memory")
#define CPC() asm volatile("cp.async.commit_group;" ::: "memory")
#define CPW1() asm volatile("cp.async.wait_group 1;" ::: "memory")
#define CPW0() asm volatile("cp.async.wait_group 0;" ::: "memory")

// ---------------------------------------------------------------------------
// Split fp32 -> bf16 hi/lo (elementwise)
// ---------------------------------------------------------------------------
__global__ void xsplit(const float4* __restrict__ in,
                       __nv_bfloat162* __restrict__ h, __nv_bfloat162* __restrict__ l, int n4)
{
    int i = blockIdx.x * blockDim.x + threadIdx.x;
    if (i >= n4) return;
    float4 v = in[i];
    __nv_bfloat16 hx = __float2bfloat16_rn(v.x);
    __nv_bfloat16 hy = __float2bfloat16_rn(v.y);
    __nv_bfloat16 hz = __float2bfloat16_rn(v.z);
    __nv_bfloat16 hw = __float2bfloat16_rn(v.w);
    __nv_bfloat16 lx = __float2bfloat16_rn(v.x - __bfloat162float(hx));
    __nv_bfloat16 ly = __float2bfloat16_rn(v.y - __bfloat162float(hy));
    __nv_bfloat16 lz = __float2bfloat16_rn(v.z - __bfloat162float(hz));
    __nv_bfloat16 lw = __float2bfloat16_rn(v.w - __bfloat162float(hw));
    h[2 * i]     = __nv_bfloat162(hx, hy);
    h[2 * i + 1] = __nv_bfloat162(hz, hw);
    l[2 * i]     = __nv_bfloat162(lx, ly);
    l[2 * i + 1] = __nv_bfloat162(lz, lw);
}

// ---------------------------------------------------------------------------
// Fused transpose + split for all 4 weights: W[k][n] -> Th/Tl[n][k] bf16
// ---------------------------------------------------------------------------
struct WPack {
    const float* W[4];
    __nv_bfloat16* Th[4];
    __nv_bfloat16* Tl[4];
};

__global__ void wsplit_all(WPack p)
{
    __shared__ float t[32][33];
    const float* W = p.W[blockIdx.z];
    __nv_bfloat16* Th = p.Th[blockIdx.z];
    __nv_bfloat16* Tl = p.Tl[blockIdx.z];
    const int n0 = blockIdx.x * 32, k0 = blockIdx.y * 32;
    const int x = threadIdx.x, y = threadIdx.y;   // 32 x 8
#pragma unroll
    for (int i = y; i < 32; i += 8)
        t[i][x] = W[(size_t)(k0 + i) * EDIM + n0 + x];
    __syncthreads();
#pragma unroll
    for (int i = y; i < 32; i += 8) {
        float v = t[x][i];
        __nv_bfloat16 hv = __float2bfloat16_rn(v);
        __nv_bfloat16 lv = __float2bfloat16_rn(v - __bfloat162float(hv));
        size_t o = (size_t)(n0 + i) * EDIM + k0 + x;
        Th[o] = hv;
        Tl[o] = lv;
    }
}

// ---------------------------------------------------------------------------
// HMMA bf16x3 GEMM + bias, cp.async double-buffered.
// blockIdx.z selects the weight/bias/output set (fused QKV).
// SPLIT=true: write bf16 hi/lo; else fp32 to Cout.
// ---------------------------------------------------------------------------
struct QKVPack {
    const __nv_bfloat16* Bh[3];
    const __nv_bfloat16* Bl[3];
    const float* bias[3];
    __nv_bfloat16* Oh[3];
    __nv_bfloat16* Ol[3];
};

#define GEMM_SMEM (2 * 65536 + 1024)

template <bool SPLIT>
__global__ __launch_bounds__(256) void hmma_gemm_bias(
    const __nv_bfloat16* __restrict__ Ah, const __nv_bfloat16* __restrict__ Al,
    QKVPack p, float* __restrict__ Cout)
{
    extern __shared__ char smem[];
    const uint32_t sbase = (smem_u32(smem) + 1023) & ~1023u;

    const int z = blockIdx.z;
    const uint4* gAh = (const uint4*)Ah;
    const uint4* gAl = (const uint4*)Al;
    const uint4* gBh = (const uint4*)p.Bh[z];
    const uint4* gBl = (const uint4*)p.Bl[z];
    const float* bias = p.bias[z];

    const int tid  = threadIdx.x;
    const int wid  = tid >> 5;
    const int lane = tid & 31;
    const int wm   = wid >> 2;
    const int wn   = wid & 3;
    const int m0   = blockIdx.y * 128;
    const int n0   = blockIdx.x * 128;

    const int a_row = lane & 15;
    const int a_kb  = (lane >> 4) * 16;
    const int b_row = (lane & 7) | ((lane & 16) >> 1);
    const int b_kb  = (lane & 8) * 2;

    float acc[4][4][4];
#pragma unroll
    for (int i = 0; i < 4; i++)
#pragma unroll
        for (int j = 0; j < 4; j++)
#pragma unroll
            for (int r = 0; r < 4; r++) acc[i][j][r] = 0.f;

    auto stage = [&](int kc, int bu) {
        const uint32_t bb = sbase + bu * 65536;
#pragma unroll
        for (int t = 0; t < 4; t++) {
            const int idx = tid + t * 256;
            const int row = idx >> 3;
            const int c16 = idx & 7;
            const uint32_t sw = sw128((uint32_t)(row * 128 + c16 * 16));
            const int ga = (m0 + row) * 128 + kc * 8 + c16;
            const int gb = (n0 + row) * 128 + kc * 8 + c16;
            CPA16(bb + sw,         gAh + ga);
            CPA16(bb + 16384 + sw, gAl + ga);
            CPA16(bb + 32768 + sw, gBh + gb);
            CPA16(bb + 49152 + sw, gBl + gb);
        }
        CPC();
    };

    stage(0, 0);

    for (int kc = 0; kc < 16; kc++) {
        if (kc < 15) { stage(kc + 1, (kc + 1) & 1); CPW1(); }
        else         { CPW0(); }
        __syncthreads();

        const uint32_t bb  = sbase + (kc & 1) * 65536;
        const uint32_t sAh = bb;
        const uint32_t sAl = bb + 16384;
        const uint32_t sBh = bb + 32768;
        const uint32_t sBl = bb + 49152;

#pragma unroll
        for (int s = 0; s < 4; s++) {
            const int kb = s * 32;
            uint32_t ah[16], al[16], bh[8], bl[8];
#pragma unroll
            for (int mf = 0; mf < 4; mf++) {
                const uint32_t off = (uint32_t)((wm * 64 + mf * 16 + a_row) * 128 + a_kb + kb);
                const uint32_t sw = sw128(off);
                ldsm4(sAh + sw, ah[mf * 4], ah[mf * 4 + 1], ah[mf * 4 + 2], ah[mf * 4 + 3]);
                ldsm4(sAl + sw, al[mf * 4], al[mf * 4 + 1], al[mf * 4 + 2], al[mf * 4 + 3]);
            }
#pragma unroll
            for (int nb = 0; nb < 2; nb++) {
                const uint32_t off = (uint32_t)((wn * 32 + nb * 16 + b_row) * 128 + b_kb + kb);
                const uint32_t sw = sw128(off);
                ldsm4(sBh + sw, bh[nb * 4], bh[nb * 4 + 1], bh[nb * 4 + 2], bh[nb * 4 + 3]);
                ldsm4(sBl + sw, bl[nb * 4], bl[nb * 4 + 1], bl[nb * 4 + 2], bl[nb * 4 + 3]);
            }
#pragma unroll
            for (int mf = 0; mf < 4; mf++)
#pragma unroll
                for (int nf = 0; nf < 4; nf++) {
                    mma16816(acc[mf][nf], &ah[mf * 4], bh[nf * 2], bh[nf * 2 + 1]);
                    mma16816(acc[mf][nf], &ah[mf * 4], bl[nf * 2], bl[nf * 2 + 1]);
                    mma16816(acc[mf][nf], &al[mf * 4], bh[nf * 2], bh[nf * 2 + 1]);
                }
        }
        __syncthreads();
    }

    const int er = lane >> 2;
    const int ec = (lane & 3) * 2;
#pragma unroll
    for (int mf = 0; mf < 4; mf++) {
#pragma unroll
        for (int nf = 0; nf < 4; nf++) {
            const int col  = n0 + wn * 32 + nf * 8 + ec;
            const float b0 = bias[col], b1 = bias[col + 1];
            const int row0 = m0 + wm * 64 + mf * 16 + er;
            float v0 = acc[mf][nf][0] + b0, v1 = acc[mf][nf][1] + b1;
            float v2 = acc[mf][nf][2] + b0, v3 = acc[mf][nf][3] + b1;
            if (SPLIT) {
                __nv_bfloat16* Oh = p.Oh[z];
                __nv_bfloat16* Ol = p.Ol[z];
                __nv_bfloat16 h0 = __float2bfloat16_rn(v0);
                __nv_bfloat16 h1 = __float2bfloat16_rn(v1);
                __nv_bfloat16 h2 = __float2bfloat16_rn(v2);
                __nv_bfloat16 h3 = __float2bfloat16_rn(v3);
                __nv_bfloat16 l0 = __float2bfloat16_rn(v0 - __bfloat162float(h0));
                __nv_bfloat16 l1 = __float2bfloat16_rn(v1 - __bfloat162float(h1));
                __nv_bfloat16 l2 = __float2bfloat16_rn(v2 - __bfloat162float(h2));
                __nv_bfloat16 l3 = __float2bfloat16_rn(v3 - __bfloat162float(h3));
                *(__nv_bfloat162*)&Oh[(size_t)row0 * EDIM + col]       = __nv_bfloat162(h0, h1);
                *(__nv_bfloat162*)&Oh[(size_t)(row0 + 8) * EDIM + col] = __nv_bfloat162(h2, h3);
                *(__nv_bfloat162*)&Ol[(size_t)row0 * EDIM + col]       = __nv_bfloat162(l0, l1);
                *(__nv_bfloat162*)&Ol[(size_t)(row0 + 8) * EDIM + col] = __nv_bfloat162(l2, l3);
            } else {
                *(float2*)&Cout[(size_t)row0 * EDIM + col]       = make_float2(v0, v1);
                *(float2*)&Cout[(size_t)(row0 + 8) * EDIM + col] = make_float2(v2, v3);
            }
        }
    }
}

// ---------------------------------------------------------------------------
// HMMA flash attention, bf16 hi/lo compensated, cp.async double-buffered K/V.
// CTA: 128 queries x one (b,h). 8 warps x 16 query rows. Key tile = 64.
// 2 CTAs/SM (launch_bounds): softmax of one CTA overlaps MMA of the other.
// Q fragments reloaded from persistent smem each tile to fit 128 regs.
// ---------------------------------------------------------------------------
#define ATT_SMEM (32768 + 2 * 32768 + 1024)

__global__ __launch_bounds__(256, 2) void attn_hmma(
    const __nv_bfloat16* __restrict__ Qh_g, const __nv_bfloat16* __restrict__ Ql_g,
    const __nv_bfloat16* __restrict__ Kh_g, const __nv_bfloat16* __restrict__ Kl_g,
    const __nv_bfloat16* __restrict__ Vh_g, const __nv_bfloat16* __restrict__ Vl_g,
    __nv_bfloat16* __restrict__ Ch_g, __nv_bfloat16* __restrict__ Cl_g)
{
    extern __shared__ char smem[];
    const uint32_t sQ  = (smem_u32(smem) + 1023) & ~1023u;
    const uint32_t sKV = sQ + 32768;

    const int tid  = threadIdx.x;
    const int lane = tid & 31;
    const int warp = tid >> 5;
    const int q0   = blockIdx.x * 128;
    const int bh   = blockIdx.y;
    const int b    = bh >> 4;
    const int h    = bh & 15;
    const int gbase = (b * SS) * 128 + h * 8;     // uint4 index of (row, h*64)

    const uint4* qh4 = (const uint4*)Qh_g;
    const uint4* ql4 = (const uint4*)Ql_g;
    const uint4* kh4 = (const uint4*)Kh_g;
    const uint4* kl4 = (const uint4*)Kl_g;
    const uint4* vh4 = (const uint4*)Vh_g;
    const uint4* vl4 = (const uint4*)Vl_g;

    // ---- stage Q (cp.async): hi rows -> sQ[0:16K), lo -> sQ[16K:32K)
#pragma unroll
    for (int t = 0; t < 8; t++) {
        const int idx  = tid + t * 256;      // 0..2047
        const int half = idx >> 10;
        const int rem  = idx & 1023;
        const int row  = rem >> 3;
        const int c16  = rem & 7;
        const uint4* src = half ? ql4 : qh4;
        const uint32_t dst = sQ + half * 16384 + (row >> 6) * 8192
                           + sw128((uint32_t)((row & 63) * 128 + c16 * 16));
        CPA16(dst, src + gbase + (q0 + row) * 128 + c16);
    }
    CPC();

    // K/V tile staging: buf layout Kh|Kl|Vh|Vl (8KB each)
    auto stageKV = [&](int kt, int bu) {
        const int k0 = kt * 64;
        const uint32_t bb = sKV + bu * 32768;
#pragma unroll
        for (int j = 0; j < 2; j++) {
            const int idx = tid + j * 256;       // 0..511
            const int row = idx >> 3;
            const int c16 = idx & 7;
            const int gsrc = gbase + (k0 + row) * 128 + c16;
            const uint32_t sw = sw128((uint32_t)(row * 128 + c16 * 16));
            CPA16(bb + sw,         kh4 + gsrc);
            CPA16(bb + 8192 + sw,  kl4 + gsrc);
            CPA16(bb + 16384 + sw, vh4 + gsrc);
            CPA16(bb + 24576 + sw, vl4 + gsrc);
        }
        CPC();
    };

    stageKV(0, 0);
    CPW0();
    __syncthreads();

    const int wr = warp * 16;
    const uint32_t qb_h = sQ + (wr >> 6) * 8192;
    const uint32_t qb_l = sQ + 16384 + (wr >> 6) * 8192;
    const int q_lrow = (wr & 63) + (lane & 15);
    const int q_lcol = ((lane >> 4) << 4);

    float o[8][4];
#pragma unroll
    for (int i = 0; i < 8; i++)
#pragma unroll
        for (int j = 0; j < 4; j++) o[i][j] = 0.f;
    float m0 = -FLT_MAX, m1 = -FLT_MAX, l0 = 0.f, l1 = 0.f;

    const int NT = SS / 64;
    for (int kt = 0; kt < NT; kt++) {
        if (kt < NT - 1) { stageKV(kt + 1, (kt + 1) & 1); CPW1(); }
        else             { CPW0(); }
        __syncthreads();

        const uint32_t bb = sKV + (kt & 1) * 32768;

        // ---- reload Q fragments from persistent smem (frees 32 regs)
        uint32_t qh[4][4], ql[4][4];
#pragma unroll
        for (int ks = 0; ks < 4; ks++) {
            const uint32_t off = sw128((uint32_t)(q_lrow * 128 + ks * 32 + q_lcol));
            ldsm4(qb_h + off, qh[ks][0], qh[ks][1], qh[ks][2], qh[ks][3]);
            ldsm4(qb_l + off, ql[ks][0], ql[ks][1], ql[ks][2], ql[ks][3]);
        }

        // ---- S = Q K^T (3-term compensated)
        float s[8][4];
#pragma unroll
        for (int i = 0; i < 8; i++)
#pragma unroll
            for (int j = 0; j < 4; j++) s[i][j] = 0.f;

        const int t8 = lane >> 3;
#pragma unroll
        for (int ks = 0; ks < 4; ks++) {
#pragma unroll
            for (int np = 0; np < 4; np++) {
                const uint32_t off = sw128((uint32_t)(
                    (np * 16 + ((t8 >> 1) << 3) + (lane & 7)) * 128 + (t8 & 1) * 16 + ks * 32));
                uint32_t h0, h1, h2, h3, e0, e1, e2, e3;
                ldsm4(bb + off, h0, h1, h2, h3);
                ldsm4(bb + 8192 + off, e0, e1, e2, e3);
                mma16816(s[2 * np],     qh[ks], h0, h1);
                mma16816(s[2 * np],     qh[ks], e0, e1);
                mma16816(s[2 * np],     ql[ks], h0, h1);
                mma16816(s[2 * np + 1], qh[ks], h2, h3);
                mma16816(s[2 * np + 1], qh[ks], e2, e3);
                mma16816(s[2 * np + 1], ql[ks], h2, h3);
            }
        }

        // ---- online softmax
        float mn0 = -FLT_MAX, mn1 = -FLT_MAX;
#pragma unroll
        for (int nf = 0; nf < 8; nf++) {
            s[nf][0] *= 0.125f; s[nf][1] *= 0.125f;
            s[nf][2] *= 0.125f; s[nf][3] *= 0.125f;
            mn0 = fmaxf(mn0, fmaxf(s[nf][0], s[nf][1]));
            mn1 = fmaxf(mn1, fmaxf(s[nf][2], s[nf][3]));
        }
        mn0 = fmaxf(mn0, __shfl_xor_sync(0xffffffffu, mn0, 1));
        mn0 = fmaxf(mn0, __shfl_xor_sync(0xffffffffu, mn0, 2));
        mn1 = fmaxf(mn1, __shfl_xor_sync(0xffffffffu, mn1, 1));
        mn1 = fmaxf(mn1, __shfl_xor_sync(0xffffffffu, mn1, 2));
        mn0 = fmaxf(m0, mn0);
        mn1 = fmaxf(m1, mn1);
        const float f0 = __expf(m0 - mn0);
        const float f1 = __expf(m1 - mn1);
        m0 = mn0; m1 = mn1;

        float rs0 = 0.f, rs1 = 0.f;
        uint32_t pah[4][4], pal[4][4];
#pragma unroll
        for (int nf = 0; nf < 8; nf++) {
            float p0 = __expf(s[nf][0] - m0);
            float p1 = __expf(s[nf][1] - m0);
            float p2 = __expf(s[nf][2] - m1);
            float p3 = __expf(s[nf][3] - m1);
            rs0 += p0 + p1;
            rs1 += p2 + p3;
            __nv_bfloat16 b0 = __float2bfloat16_rn(p0);
            __nv_bfloat16 b1 = __float2bfloat16_rn(p1);
            __nv_bfloat16 b2 = __float2bfloat16_rn(p2);
            __nv_bfloat16 b3 = __float2bfloat16_rn(p3);
            __nv_bfloat16 c0 = __float2bfloat16_rn(p0 - __bfloat162float(b0));
            __nv_bfloat16 c1 = __float2bfloat16_rn(p1 - __bfloat162float(b1));
            __nv_bfloat16 c2 = __float2bfloat16_rn(p2 - __bfloat162float(b2));
            __nv_bfloat16 c3 = __float2bfloat16_rn(p3 - __bfloat162float(b3));
            const int kf = nf >> 1;
            const int rr = (nf & 1) * 2;
            pah[kf][rr]     = packbf(b0, b1);
            pah[kf][rr + 1] = packbf(b2, b3);
            pal[kf][rr]     = packbf(c0, c1);
            pal[kf][rr + 1] = packbf(c2, c3);
        }
        rs0 += __shfl_xor_sync(0xffffffffu, rs0, 1);
        rs0 += __shfl_xor_sync(0xffffffffu, rs0, 2);
        rs1 += __shfl_xor_sync(0xffffffffu, rs1, 1);
        rs1 += __shfl_xor_sync(0xffffffffu, rs1, 2);
        l0 = l0 * f0 + rs0;
        l1 = l1 * f1 + rs1;
#pragma unroll
        for (int nf = 0; nf < 8; nf++) {
            o[nf][0] *= f0; o[nf][1] *= f0;
            o[nf][2] *= f1; o[nf][3] *= f1;
        }

        // ---- O += P V (3-term compensated)
#pragma unroll
        for (int kf = 0; kf < 4; kf++) {
#pragma unroll
            for (int np = 0; np < 4; np++) {
                const uint32_t off = sw128((uint32_t)(
                    (kf * 16 + (lane & 8) + (lane & 7)) * 128 + np * 32 + ((lane >> 4) << 4)));
                uint32_t v0, v1, v2, v3, w0, w1, w2, w3;
                ldsm4t(bb + 16384 + off, v0, v1, v2, v3);
                ldsm4t(bb + 24576 + off, w0, w1, w2, w3);
                mma16816(o[2 * np],     pah[kf], v0, v1);
                mma16816(o[2 * np],     pah[kf], w0, w1);
                mma16816(o[2 * np],     pal[kf], v0, v1);
                mma16816(o[2 * np + 1], pah[kf], v2, v3);
                mma16816(o[2 * np + 1], pah[kf], w2, w3);
                mma16816(o[2 * np + 1], pal[kf], v2, v3);
            }
        }
        __syncthreads();
    }

    // ---- epilogue: normalize, hi/lo split, store
    const float inv0 = 1.f / l0;
    const float inv1 = 1.f / l1;
    const int row0 = q0 + wr + (lane >> 2);
    const int colb = h * 64 + (lane & 3) * 2;
#pragma unroll
    for (int nf = 0; nf < 8; nf++) {
        const int col = colb + nf * 8;
        float v0 = o[nf][0] * inv0, v1 = o[nf][1] * inv0;
        float v2 = o[nf][2] * inv1, v3 = o[nf][3] * inv1;
        __nv_bfloat16 h0 = __float2bfloat16_rn(v0);
        __nv_bfloat16 h1 = __float2bfloat16_rn(v1);
        __nv_bfloat16 h2 = __float2bfloat16_rn(v2);
        __nv_bfloat16 h3 = __float2bfloat16_rn(v3);
        __nv_bfloat16 e0 = __float2bfloat16_rn(v0 - __bfloat162float(h0));
        __nv_bfloat16 e1 = __float2bfloat16_rn(v1 - __bfloat162float(h1));
        __nv_bfloat16 e2 = __float2bfloat16_rn(v2 - __bfloat162float(h2));
        __nv_bfloat16 e3 = __float2bfloat16_rn(v3 - __bfloat162float(h3));
        const size_t r0i = (size_t)(b * SS + row0) * EDIM + col;
        const size_t r1i = (size_t)(b * SS + row0 + 8) * EDIM + col;
        *(__nv_bfloat162*)&Ch_g[r0i] = __nv_bfloat162(h0, h1);
        *(__nv_bfloat162*)&Ch_g[r1i] = __nv_bfloat162(h2, h3);
        *(__nv_bfloat162*)&Cl_g[r0i] = __nv_bfloat162(e0, e1);
        *(__nv_bfloat162*)&Cl_g[r1i] = __nv_bfloat162(e2, e3);
    }
}

// ---------------------------------------------------------------------------
// Launch sequence (graph-capturable, no allocs)
// ---------------------------------------------------------------------------
extern "C" void kernel_launch(void* const* d_in, const int* in_sizes, int n_in,
                              void* d_out, int out_size)
{
    const float* x  = (const float*)d_in[0];
    const float* Wq = (const float*)d_in[1];
    const float* bq = (const float*)d_in[2];
    const float* Wk = (const float*)d_in[3];
    const float* bk = (const float*)d_in[4];
    const float* Wv = (const float*)d_in[5];
    const float* bv = (const float*)d_in[6];
    const float* Wo = (const float*)d_in[7];
    const float* bo = (const float*)d_in[8];
    float* out = (float*)d_out;

    __nv_bfloat16 *xh, *xl, *ch, *cl;
    __nv_bfloat16 *qh, *qlp, *kh, *kl, *vh, *vl;
    __nv_bfloat16 *wqh, *wql, *wkh, *wkl, *wvh, *wvl, *woh, *wol;
    cudaGetSymbolAddress((void**)&xh, g_xh);   cudaGetSymbolAddress((void**)&xl, g_xl);
    cudaGetSymbolAddress((void**)&ch, g_ch);   cudaGetSymbolAddress((void**)&cl, g_cl);
    cudaGetSymbolAddress((void**)&qh, g_Qh);   cudaGetSymbolAddress((void**)&qlp, g_Ql);
    cudaGetSymbolAddress((void**)&kh, g_Kh);   cudaGetSymbolAddress((void**)&kl, g_Kl);
    cudaGetSymbolAddress((void**)&vh, g_Vh);   cudaGetSymbolAddress((void**)&vl, g_Vl);
    cudaGetSymbolAddress((void**)&wqh, g_Wqh); cudaGetSymbolAddress((void**)&wql, g_Wql);
    cudaGetSymbolAddress((void**)&wkh, g_Wkh); cudaGetSymbolAddress((void**)&wkl, g_Wkl);
    cudaGetSymbolAddress((void**)&wvh, g_Wvh); cudaGetSymbolAddress((void**)&wvl, g_Wvl);
    cudaGetSymbolAddress((void**)&woh, g_Woh); cudaGetSymbolAddress((void**)&wol, g_Wol);

    static int attr_set = 0;
    if (!attr_set) {
        cudaFuncSetAttribute(hmma_gemm_bias<true>,
                             cudaFuncAttributeMaxDynamicSharedMemorySize, GEMM_SMEM);
        cudaFuncSetAttribute(hmma_gemm_bias<false>,
                             cudaFuncAttributeMaxDynamicSharedMemorySize, GEMM_SMEM);
        cudaFuncSetAttribute(attn_hmma,
                             cudaFuncAttributeMaxDynamicSharedMemorySize, ATT_SMEM);
        attr_set = 1;
    }

    // 1) split x; transpose+split all weights (one launch)
    const int n4 = MTOT * EDIM / 4;
    xsplit<<<(n4 + 255) / 256, 256>>>((const float4*)x,
        (__nv_bfloat162*)xh, (__nv_bfloat162*)xl, n4);
    WPack wp;
    wp.W[0] = Wq; wp.Th[0] = wqh; wp.Tl[0] = wql;
    wp.W[1] = Wk; wp.Th[1] = wkh; wp.Tl[1] = wkl;
    wp.W[2] = Wv; wp.Th[2] = wvh; wp.Tl[2] = wvl;
    wp.W[3] = Wo; wp.Th[3] = woh; wp.Tl[3] = wol;
    wsplit_all<<<dim3(EDIM / 32, EDIM / 32, 4), dim3(32, 8)>>>(wp);

    // 2) fused Q/K/V projections (one launch, z selects set)
    QKVPack pq;
    pq.Bh[0] = wqh; pq.Bl[0] = wql; pq.bias[0] = bq; pq.Oh[0] = qh; pq.Ol[0] = qlp;
    pq.Bh[1] = wkh; pq.Bl[1] = wkl; pq.bias[1] = bk; pq.Oh[1] = kh; pq.Ol[1] = kl;
    pq.Bh[2] = wvh; pq.Bl[2] = wvl; pq.bias[2] = bv; pq.Oh[2] = vh; pq.Ol[2] = vl;
    hmma_gemm_bias<true><<<dim3(EDIM / 128, MTOT / 128, 3), 256, GEMM_SMEM>>>(
        xh, xl, pq, nullptr);

    // 3) attention on tensor cores (2 CTAs/SM)
    attn_hmma<<<dim3(SS / 128, BB * HEADS), 256, ATT_SMEM>>>(
        qh, qlp, kh, kl, vh, vl, ch, cl);

    // 4) output projection, fp32 output
    QKVPack po;
    po.Bh[0] = woh; po.Bl[0] = wol; po.bias[0] = bo; po.Oh[0] = nullptr; po.Ol[0] = nullptr;
    po.Bh[1] = po.Bh[2] = nullptr; po.Bl[1] = po.Bl[2] = nullptr;
    po.bias[1] = po.bias[2] = nullptr; po.Oh[1] = po.Oh[2] = nullptr; po.Ol[1] = po.Ol[2] = nullptr;
    hmma_gemm_bias<false><<<dim3(EDIM / 128, MTOT / 128, 1), 256, GEMM_SMEM>>>(
        ch, cl, po, out);
}